// round 2
// baseline (speedup 1.0000x reference)
#include <cuda_runtime.h>
#include <math.h>

#define NN 1024
#define DIM 512
#define HH 8
#define DD 64
#define CC 64
#define SCALE 0.125f
#define NEGF -1e30f

// ---------------- scratch (static device arrays; no allocation) ----------------
__device__ float g_xr [NN*DIM];      // residual after lambda mix
__device__ float g_xn [NN*DIM];      // rmsnorm output (reused for 2nd norm)
__device__ float g_qnh[NN*DIM];
__device__ float g_knh[NN*DIM];
__device__ float g_vnh[NN*DIM];
__device__ float g_q  [HH*NN*DD];    // [h][n][d], roped
__device__ float g_k  [HH*NN*DD];
__device__ float g_v  [HH*NN*DD];
__device__ float g_gate[NN*24];
__device__ float g_ckf[HH*65*DD];    // row 0 = k_mem, rows 1..64 = compressed k
__device__ float g_cvf[HH*65*DD];
__device__ float g_cout[HH*NN*DD];
__device__ float g_fout[HH*NN*DD];
__device__ float g_sout[HH*NN*DD];
__device__ int   g_sel [HH*NN*8];
__device__ int   g_nval[HH*NN];
__device__ float g_o  [NN*DIM];
__device__ float g_x2 [NN*DIM];
__device__ float g_h  [NN*2048];

// ---------------- prelude: x = l0*x + l1*x0 ; xn = rmsnorm(x) ----------------
__global__ void k_prelude(const float* __restrict__ x, const float* __restrict__ x0,
                          const float* __restrict__ lam) {
    int n = blockIdx.x, tid = threadIdx.x; // 128 threads
    __shared__ float red[128];
    float l0 = lam[0], l1 = lam[1];
    float v[4]; float ss = 0.f;
#pragma unroll
    for (int r = 0; r < 4; r++) {
        int d = tid + r*128;
        float t = l0*x[n*DIM+d] + l1*x0[n*DIM+d];
        v[r] = t; g_xr[n*DIM+d] = t; ss += t*t;
    }
    red[tid] = ss; __syncthreads();
    for (int s = 64; s > 0; s >>= 1) { if (tid < s) red[tid] += red[tid+s]; __syncthreads(); }
    float rms = rsqrtf(red[0]*(1.f/512.f) + 1e-6f);
#pragma unroll
    for (int r = 0; r < 4; r++) { int d = tid + r*128; g_xn[n*DIM+d] = v[r]*rms; }
}

__global__ void k_rmsnorm2() {
    int n = blockIdx.x, tid = threadIdx.x; // 128 threads
    __shared__ float red[128];
    float v[4]; float ss = 0.f;
#pragma unroll
    for (int r = 0; r < 4; r++) { int d = tid + r*128; float t = g_x2[n*DIM+d]; v[r]=t; ss += t*t; }
    red[tid] = ss; __syncthreads();
    for (int s = 64; s > 0; s >>= 1) { if (tid < s) red[tid] += red[tid+s]; __syncthreads(); }
    float rms = rsqrtf(red[0]*(1.f/512.f) + 1e-6f);
#pragma unroll
    for (int r = 0; r < 4; r++) { int d = tid + r*128; g_xn[n*DIM+d] = v[r]*rms; }
}

// ---------------- generic SGEMM: C = A@B (+bias) (+relu^2) (+R) ----------------
// row-major; BM=BN=64, BK=16, 256 threads, 4x4 microtile. K must be %16==0.
__global__ void sgemm(const float* __restrict__ A, const float* __restrict__ B,
                      const float* __restrict__ bias, const float* __restrict__ R,
                      float* __restrict__ C, int M, int N, int K, int relu2) {
    __shared__ float As[16][68];
    __shared__ float Bs[16][64];
    int bx = blockIdx.x, by = blockIdx.y;
    int tid = threadIdx.x;
    int tx = tid & 15, ty = tid >> 4;
    int rowBase = by*64, colBase = bx*64;
    float acc[4][4] = {};
    for (int k0 = 0; k0 < K; k0 += 16) {
        {   // A tile -> As[k][m]
            int m = tid >> 2, kq = tid & 3;
            int gr = rowBase + m, gc = k0 + kq*4;
            float4 av = make_float4(0.f,0.f,0.f,0.f);
            if (gr < M) av = *(const float4*)(A + (size_t)gr*K + gc);
            As[kq*4+0][m] = av.x; As[kq*4+1][m] = av.y;
            As[kq*4+2][m] = av.z; As[kq*4+3][m] = av.w;
        }
        {   // B tile -> Bs[k][n]
            int kk = tid >> 4, nq = tid & 15;
            int gr = k0 + kk, gcb = colBase + nq*4;
            float4 bv;
            if (gcb + 3 < N) {
                bv = *(const float4*)(B + (size_t)gr*N + gcb);
            } else {
                float t[4] = {0.f,0.f,0.f,0.f};
                for (int q = 0; q < 4; q++) if (gcb + q < N) t[q] = B[(size_t)gr*N + gcb + q];
                bv = make_float4(t[0],t[1],t[2],t[3]);
            }
            *(float4*)&Bs[kk][nq*4] = bv;
        }
        __syncthreads();
#pragma unroll
        for (int kk = 0; kk < 16; kk++) {
            float4 a = *(const float4*)&As[kk][ty*4];
            float4 b = *(const float4*)&Bs[kk][tx*4];
            acc[0][0]+=a.x*b.x; acc[0][1]+=a.x*b.y; acc[0][2]+=a.x*b.z; acc[0][3]+=a.x*b.w;
            acc[1][0]+=a.y*b.x; acc[1][1]+=a.y*b.y; acc[1][2]+=a.y*b.z; acc[1][3]+=a.y*b.w;
            acc[2][0]+=a.z*b.x; acc[2][1]+=a.z*b.y; acc[2][2]+=a.z*b.z; acc[2][3]+=a.z*b.w;
            acc[3][0]+=a.w*b.x; acc[3][1]+=a.w*b.y; acc[3][2]+=a.w*b.z; acc[3][3]+=a.w*b.w;
        }
        __syncthreads();
    }
#pragma unroll
    for (int i = 0; i < 4; i++) {
        int r = rowBase + ty*4 + i; if (r >= M) continue;
#pragma unroll
        for (int j = 0; j < 4; j++) {
            int c = colBase + tx*4 + j; if (c >= N) continue;
            float v = acc[i][j];
            if (bias) v += bias[c];
            if (relu2) { v = fmaxf(v, 0.f); v *= v; }
            if (R) v += R[(size_t)r*N + c];
            C[(size_t)r*N + c] = v;
        }
    }
}

// ---------------- rope + [N,H*D] -> [H,N,D] transpose ----------------
__global__ void k_rope() {
    int n = blockIdx.x, h = blockIdx.y, d = threadIdx.x; // 64 threads
    int src = n*DIM + h*64 + d;
    int dst = (h*NN + n)*64 + d;
    g_v[dst] = g_vnh[src];
    if (d < 32) {
        float inv = expf(-(float)d * (9.210340371976184f/32.f)); // 10000^{-d/32}
        float ang = (float)n * inv;
        float cs = cosf(ang), sn = sinf(ang);
        float a = g_qnh[src], b = g_qnh[src+32];
        g_q[dst]    = a*cs - b*sn;
        g_q[dst+32] = b*cs + a*sn;
        a = g_knh[src]; b = g_knh[src+32];
        g_k[dst]    = a*cs - b*sn;
        g_k[dst+32] = b*cs + a*sn;
    }
}

// ---------------- compressed K/V: (kb+pos).flat @ Wck + bck per (h,c) ----------------
__global__ void k_ckcv(const float* __restrict__ kpos, const float* __restrict__ vpos,
                       const float* __restrict__ Wck, const float* __restrict__ bck,
                       const float* __restrict__ Wcv, const float* __restrict__ bcv,
                       const float* __restrict__ kmem, const float* __restrict__ vmem) {
    __shared__ float kbs[1024], vbs[1024];
    int row = blockIdx.x, h = row >> 6, c = row & 63, tid = threadIdx.x; // 64 threads
    for (int e = tid; e < 1024; e += 64) {
        int j = e >> 6, d = e & 63;
        float kv = g_k[(h*NN + c*16 + j)*64 + d] + kpos[h*1024 + e];
        float vv = g_v[(h*NN + c*16 + j)*64 + d] + vpos[h*1024 + e];
        kbs[e] = kv; vbs[e] = vv;
    }
    __syncthreads();
    int d = tid;
    float ak = bck[d], av = bcv[d];
#pragma unroll 4
    for (int e = 0; e < 1024; e++) {
        ak += kbs[e] * Wck[e*64 + d];
        av += vbs[e] * Wcv[e*64 + d];
    }
    g_ckf[(h*65 + 1 + c)*64 + d] = ak;
    g_cvf[(h*65 + 1 + c)*64 + d] = av;
    if (c == 0) {
        g_ckf[h*65*64 + d] = kmem[h*64 + d];
        g_cvf[h*65*64 + d] = vmem[h*64 + d];
    }
}

// ---------------- compressed attention + top-8 selection ----------------
__global__ void k_compressed() {
    int i = blockIdx.x, h = blockIdx.y, tid = threadIdx.x; // 128 threads
    __shared__ float qs[64], attn[65], red[128];
    __shared__ unsigned long long keys[64], tr[64];
    if (tid < 64) qs[tid] = g_q[(h*NN + i)*64 + tid];
    __syncthreads();
    int own = i >> 4; // number of fully-past blocks
    if (tid < 65) {
        float s = NEGF;
        if (tid == 0 || (tid - 1) < own) {
            const float* kr = g_ckf + (h*65 + tid)*64;
            float acc = 0.f;
#pragma unroll
            for (int d = 0; d < 64; d++) acc += qs[d]*kr[d];
            s = acc * SCALE;
        }
        attn[tid] = s;
    }
    __syncthreads();
    red[tid] = (tid < 65) ? attn[tid] : NEGF;
    __syncthreads();
    for (int s = 64; s > 0; s >>= 1) { if (tid < s) red[tid] = fmaxf(red[tid], red[tid+s]); __syncthreads(); }
    float m = red[0]; __syncthreads();
    float e = 0.f;
    if (tid < 65) { e = __expf(attn[tid] - m); attn[tid] = e; }
    red[tid] = e; __syncthreads();
    for (int s = 64; s > 0; s >>= 1) { if (tid < s) red[tid] += red[tid+s]; __syncthreads(); }
    float inv = 1.f / red[0];
    __syncthreads();
    if (tid < 65) attn[tid] *= inv;
    __syncthreads();
    if (tid < 64) {
        float acc = 0.f;
        for (int j = 0; j <= own; j++) acc += attn[j] * g_cvf[(h*65 + j)*64 + tid];
        g_cout[(h*NN + i)*64 + tid] = acc;
    }
    // top-8 among past blocks c in [0, own), value desc, index asc tie-break
    if (tid < 64) {
        unsigned long long kk = 0ULL;
        if (tid < own) {
            unsigned fb = __float_as_uint(attn[1 + tid]); // >= 0
            kk = ((unsigned long long)fb << 32) | (unsigned)(0xFFFFFFFFu - tid);
        }
        keys[tid] = kk;
    }
    __syncthreads();
    int base = (h*NN + i)*8;
    int nv = 0;
    for (int t = 0; t < 8; t++) {
        if (tid < 64) tr[tid] = keys[tid];
        __syncthreads();
        for (int s = 32; s > 0; s >>= 1) {
            if (tid < s && tr[tid+s] > tr[tid]) tr[tid] = tr[tid+s];
            __syncthreads();
        }
        unsigned long long best = tr[0];
        if (best) {
            int c = (int)(0xFFFFFFFFu - (unsigned)(best & 0xFFFFFFFFu));
            nv = t + 1;
            if (tid == 0) { g_sel[base + t] = c; keys[c] = 0ULL; }
        } else if (tid == 0) g_sel[base + t] = 0;
        __syncthreads();
    }
    if (tid == 0) g_nval[h*NN + i] = nv;
}

// ---------------- fine attention over <=144 gathered keys ----------------
__global__ void k_fine() {
    int i = blockIdx.x, h = blockIdx.y, tid = threadIdx.x; // 256 threads
    int w = tid >> 5, lane = tid & 31;
    __shared__ float qs[64], sc[160], red[256], wacc[8][64];
    __shared__ int toks[160];
    if (tid < 64) qs[tid] = g_q[(h*NN + i)*64 + tid];
    int own = i >> 4, nv = g_nval[h*NN + i], base = (h*NN + i)*8;
    int nk = nv*16 + (i & 15) + 1;
    if (tid < nk) {
        int t;
        if (tid < nv*16) t = g_sel[base + (tid >> 4)]*16 + (tid & 15);
        else             t = own*16 + (tid - nv*16);
        toks[tid] = t;
    }
    __syncthreads();
    for (int kk = w; kk < nk; kk += 8) {
        const float* kr = g_k + (h*NN + toks[kk])*64;
        float p = qs[lane]*kr[lane] + qs[lane+32]*kr[lane+32];
#pragma unroll
        for (int o = 16; o > 0; o >>= 1) p += __shfl_down_sync(0xFFFFFFFFu, p, o);
        if (lane == 0) sc[kk] = p * SCALE;
    }
    __syncthreads();
    red[tid] = (tid < nk) ? sc[tid] : NEGF;
    __syncthreads();
    for (int s = 128; s > 0; s >>= 1) { if (tid < s) red[tid] = fmaxf(red[tid], red[tid+s]); __syncthreads(); }
    float m = red[0]; __syncthreads();
    float e = 0.f;
    if (tid < nk) e = __expf(sc[tid] - m);
    red[tid] = e; __syncthreads();
    for (int s = 128; s > 0; s >>= 1) { if (tid < s) red[tid] += red[tid+s]; __syncthreads(); }
    float inv = 1.f / red[0];
    __syncthreads();
    if (tid < nk) sc[tid] = e * inv;
    __syncthreads();
    float a0 = 0.f, a1 = 0.f;
    for (int kk = w; kk < nk; kk += 8) {
        const float* vr = g_v + (h*NN + toks[kk])*64;
        float p = sc[kk];
        a0 += p * vr[lane]; a1 += p * vr[lane+32];
    }
    wacc[w][lane] = a0; wacc[w][lane+32] = a1;
    __syncthreads();
    if (tid < 64) {
        float s = 0.f;
#pragma unroll
        for (int ww = 0; ww < 8; ww++) s += wacc[ww][tid];
        g_fout[(h*NN + i)*64 + tid] = s;
    }
}

// ---------------- sliding-window attention, flash-style, 16-query tiles ----------------
__global__ void k_sliding() {
    int qt = blockIdx.x, h = blockIdx.y, tid = threadIdx.x; // 128 threads
    int i0 = qt*16;
    __shared__ float qs[16][65], ks[16][65], vs[16][65], accs[16][64], sc[16][17];
    __shared__ float mrow[16], lrow[16], alpha[16];
#pragma unroll
    for (int r = 0; r < 8; r++) {
        int idx = tid + r*128; int qi = idx >> 6, d = idx & 63;
        qs[qi][d] = g_q[(h*NN + i0 + qi)*64 + d];
        accs[qi][d] = 0.f;
    }
    if (tid < 16) { mrow[tid] = -INFINITY; lrow[tid] = 0.f; }
    __syncthreads();
    int t0 = (qt > 16) ? (qt - 16) : 0;
    for (int t = t0; t <= qt; t++) {
#pragma unroll
        for (int r = 0; r < 8; r++) {
            int idx = tid + r*128; int kj = idx >> 6, d = idx & 63;
            ks[kj][d] = g_k[(h*NN + t*16 + kj)*64 + d];
            vs[kj][d] = g_v[(h*NN + t*16 + kj)*64 + d];
        }
        __syncthreads();
#pragma unroll
        for (int r = 0; r < 2; r++) {
            int p = tid + r*128; int qi = p >> 4, kj = p & 15;
            int j = t*16 + kj, ii = i0 + qi;
            float s = 0.f;
#pragma unroll
            for (int d = 0; d < 64; d++) s += qs[qi][d]*ks[kj][d];
            bool vis = (j <= ii) && (ii - j < 256);
            sc[qi][kj] = vis ? s*SCALE : -INFINITY;
        }
        __syncthreads();
        if (tid < 16) {
            int qi = tid;
            float rm = -INFINITY;
            for (int kj = 0; kj < 16; kj++) rm = fmaxf(rm, sc[qi][kj]);
            float nm = fmaxf(mrow[qi], rm);
            float al, rs = 0.f;
            if (nm == -INFINITY) {
                al = 1.f;
                for (int kj = 0; kj < 16; kj++) sc[qi][kj] = 0.f;
            } else {
                al = __expf(mrow[qi] - nm);
                for (int kj = 0; kj < 16; kj++) {
                    float ee = __expf(sc[qi][kj] - nm);
                    sc[qi][kj] = ee; rs += ee;
                }
            }
            mrow[qi] = nm; alpha[qi] = al; lrow[qi] = lrow[qi]*al + rs;
        }
        __syncthreads();
#pragma unroll
        for (int r = 0; r < 8; r++) {
            int idx = tid + r*128; int qi = idx >> 6, d = idx & 63;
            float a = accs[qi][d]*alpha[qi];
#pragma unroll
            for (int kj = 0; kj < 16; kj++) a += sc[qi][kj]*vs[kj][d];
            accs[qi][d] = a;
        }
        __syncthreads();
    }
#pragma unroll
    for (int r = 0; r < 8; r++) {
        int idx = tid + r*128; int qi = idx >> 6, d = idx & 63;
        g_sout[(h*NN + i0 + qi)*64 + d] = accs[qi][d] / lrow[qi];
    }
}

// ---------------- gated combine -> [N, H*D] ----------------
__global__ void k_combine() {
    int n = blockIdx.x, c = threadIdx.x; // 512 threads
    int h = c >> 6, d = c & 63;
    const float* gl = g_gate + n*24 + h*3;
    float g0 = 1.f/(1.f + __expf(-gl[0]));
    float g1 = 1.f/(1.f + __expf(-gl[1]));
    float g2 = 1.f/(1.f + __expf(-gl[2]));
    int idx = (h*NN + n)*64 + d;
    g_o[n*DIM + c] = g0*g_cout[idx] + g1*g_fout[idx] + g2*g_sout[idx];
}

// ---------------- launch ----------------
extern "C" void kernel_launch(void* const* d_in, const int* in_sizes, int n_in,
                              void* d_out, int out_size) {
    const float* x    = (const float*)d_in[0];
    /* d_in[1] = ve (unused in reference) */
    const float* x0   = (const float*)d_in[2];
    const float* lam  = (const float*)d_in[3];
    const float* Wq   = (const float*)d_in[4];
    const float* Wk   = (const float*)d_in[5];
    const float* Wv   = (const float*)d_in[6];
    const float* Wo   = (const float*)d_in[7];
    const float* Wg   = (const float*)d_in[8];
    const float* kpos = (const float*)d_in[9];
    const float* vpos = (const float*)d_in[10];
    const float* Wck  = (const float*)d_in[11];
    const float* bck  = (const float*)d_in[12];
    const float* Wcv  = (const float*)d_in[13];
    const float* bcv  = (const float*)d_in[14];
    const float* kmem = (const float*)d_in[15];
    const float* vmem = (const float*)d_in[16];
    const float* W1   = (const float*)d_in[17];
    const float* W2   = (const float*)d_in[18];
    float* out = (float*)d_out;

    float *p_xr, *p_xn, *p_qnh, *p_knh, *p_vnh, *p_gate, *p_o, *p_x2, *p_h;
    cudaGetSymbolAddress((void**)&p_xr,  g_xr);
    cudaGetSymbolAddress((void**)&p_xn,  g_xn);
    cudaGetSymbolAddress((void**)&p_qnh, g_qnh);
    cudaGetSymbolAddress((void**)&p_knh, g_knh);
    cudaGetSymbolAddress((void**)&p_vnh, g_vnh);
    cudaGetSymbolAddress((void**)&p_gate,g_gate);
    cudaGetSymbolAddress((void**)&p_o,   g_o);
    cudaGetSymbolAddress((void**)&p_x2,  g_x2);
    cudaGetSymbolAddress((void**)&p_h,   g_h);

    k_prelude<<<NN, 128>>>(x, x0, lam);

    sgemm<<<dim3(8,16), 256>>>(p_xn, Wq, nullptr, nullptr, p_qnh, 1024, 512, 512, 0);
    sgemm<<<dim3(8,16), 256>>>(p_xn, Wk, nullptr, nullptr, p_knh, 1024, 512, 512, 0);
    sgemm<<<dim3(8,16), 256>>>(p_xn, Wv, nullptr, nullptr, p_vnh, 1024, 512, 512, 0);
    sgemm<<<dim3(1,16), 256>>>(p_xn, Wg, nullptr, nullptr, p_gate, 1024, 24, 512, 0);

    k_rope<<<dim3(NN, HH), 64>>>();
    k_ckcv<<<HH*CC, 64>>>(kpos, vpos, Wck, bck, Wcv, bcv, kmem, vmem);

    k_compressed<<<dim3(NN, HH), 128>>>();
    k_fine<<<dim3(NN, HH), 256>>>();
    k_sliding<<<dim3(NN/16, HH), 128>>>();
    k_combine<<<NN, 512>>>();

    // x2 = xr + o @ Wo
    sgemm<<<dim3(8,16), 256>>>(p_o, Wo, nullptr, p_xr, p_x2, 1024, 512, 512, 0);
    k_rmsnorm2<<<NN, 128>>>();
    // h = relu(xn @ W1)^2
    sgemm<<<dim3(32,16), 256>>>(p_xn, W1, nullptr, nullptr, p_h, 1024, 2048, 512, 1);
    // out = x2 + h @ W2
    sgemm<<<dim3(8,16), 256>>>(p_h, W2, nullptr, p_x2, out, 1024, 512, 2048, 0);
}

// round 7
// speedup vs baseline: 1.1106x; 1.1106x over previous
#include <cuda_runtime.h>
#include <cuda_bf16.h>
#include <stdint.h>
#include <math.h>

#define NN 1024
#define DIM 512
#define HH 8
#define DD 64
#define CC 64
#define SCALE 0.125f
#define NEGF -1e30f

// ---------------- scratch ----------------
__device__ float g_xr [NN*DIM];
__device__ float g_xn [NN*DIM];            // fp32 (Wg path)
__device__ __nv_bfloat16 g_xnh[NN*DIM], g_xnl[NN*DIM];
__device__ float g_qkv[NN*1536];
__device__ float g_q  [HH*NN*DD];
__device__ float g_k  [HH*NN*DD];
__device__ float g_v  [HH*NN*DD];
__device__ float g_gate[NN*24];
__device__ float g_ckf[HH*65*DD];
__device__ float g_cvf[HH*65*DD];
__device__ float g_cout[HH*NN*DD];
__device__ float g_fout[HH*NN*DD];
__device__ float g_sout[HH*NN*DD];
__device__ int   g_sel [HH*NN*8];
__device__ int   g_nval[HH*NN];
__device__ __nv_bfloat16 g_ohi[NN*DIM], g_olo[NN*DIM];
__device__ float g_x2 [NN*DIM];
__device__ __nv_bfloat16 g_hhi[NN*2048], g_hlo[NN*2048];
// transposed bf16 hi/lo weights: [Nout][K]
__device__ __nv_bfloat16 g_wqkvTh[1536*512], g_wqkvTl[1536*512];
__device__ __nv_bfloat16 g_woTh[512*512],    g_woTl[512*512];
__device__ __nv_bfloat16 g_w1Th[2048*512],   g_w1Tl[2048*512];
__device__ __nv_bfloat16 g_w2Th[512*2048],   g_w2Tl[512*2048];

// ---------------- helpers ----------------
__device__ __forceinline__ uint32_t smem_u32(const void* p) {
    uint32_t a;
    asm("{ .reg .u64 t; cvta.to.shared.u64 t, %1; cvt.u32.u64 %0, t; }" : "=r"(a) : "l"(p));
    return a;
}
__device__ __forceinline__ uint32_t swz(uint32_t off) { return off ^ ((off >> 3) & 0x70); }

#define LDSM_X4(r, addr) \
    asm volatile("ldmatrix.sync.aligned.m8n8.x4.shared.b16 {%0,%1,%2,%3}, [%4];" \
        : "=r"((r)[0]),"=r"((r)[1]),"=r"((r)[2]),"=r"((r)[3]) : "r"(addr))
#define LDSM_X2(r, addr) \
    asm volatile("ldmatrix.sync.aligned.m8n8.x2.shared.b16 {%0,%1}, [%2];" \
        : "=r"((r)[0]),"=r"((r)[1]) : "r"(addr))

__device__ __forceinline__ void mma16816(float* d, const uint32_t* a, const uint32_t* b) {
    asm volatile("mma.sync.aligned.m16n8k16.row.col.f32.bf16.bf16.f32 "
        "{%0,%1,%2,%3}, {%4,%5,%6,%7}, {%8,%9}, {%0,%1,%2,%3};"
        : "+f"(d[0]),"+f"(d[1]),"+f"(d[2]),"+f"(d[3])
        : "r"(a[0]),"r"(a[1]),"r"(a[2]),"r"(a[3]), "r"(b[0]),"r"(b[1]));
}
__device__ __forceinline__ void split_bf(float x, __nv_bfloat16& h, __nv_bfloat16& l) {
    h = __float2bfloat16(x);
    l = __float2bfloat16(x - __bfloat162float(h));
}

// ---------------- weight transpose + bf16 split: dst[n][k] = split(src[k][n]) ----------------
__global__ void k_convT(const float* __restrict__ src, __nv_bfloat16* __restrict__ dhi,
                        __nv_bfloat16* __restrict__ dlo, int K, int N, int rowOff) {
    int idx = blockIdx.x*256 + threadIdx.x;
    if (idx >= K*N) return;
    int k = idx / N, n = idx - k*N;
    __nv_bfloat16 h, l; split_bf(src[idx], h, l);
    size_t d = (size_t)(rowOff + n)*K + k;
    dhi[d] = h; dlo[d] = l;
}

// ---------------- HMMA GEMM: C[1024, Nfull], CTA tile 128 x TN, BK=64 ----------------
// A: [M][K] bf16 hi/lo row-major.  B: [Nout][K] bf16 hi/lo row-major.
// 3-term split: Ah*Bh + Al*Bh + Ah*Bl.
// MODE 0: Cf = acc.  MODE 1: Cf = acc + R.  MODE 2: Chi/Clo = split(relu(acc)^2).
template<int TN, int MODE>
__global__ void __launch_bounds__(256)
hm_gemm(const __nv_bfloat16* __restrict__ Ahi, const __nv_bfloat16* __restrict__ Alo,
        const __nv_bfloat16* __restrict__ Bhi, const __nv_bfloat16* __restrict__ Blo,
        const float* __restrict__ R, float* __restrict__ Cf,
        __nv_bfloat16* __restrict__ Chi, __nv_bfloat16* __restrict__ Clo,
        int K, int Nfull) {
    constexpr int NT = TN / 16;         // n-tiles (m8n8 cols) per warp
    extern __shared__ char dsm[];
    char* pAh = dsm;                    // 128 rows x 128B
    char* pAl = dsm + 16384;
    char* pBh = dsm + 32768;            // TN rows x 128B
    char* pBl = dsm + 32768 + TN*128;
    const uint32_t sb = smem_u32(dsm);
    const uint32_t A_HI = sb, A_LO = sb + 16384, B_HI = sb + 32768, B_LO = B_HI + TN*128;

    int tid = threadIdx.x, wid = tid >> 5, lane = tid & 31;
    int wm = wid & 3, wn = wid >> 2;    // warp grid 4 (M) x 2 (N)
    int rowBase = blockIdx.y*128, colBase = blockIdx.x*TN;

    const uint4* A4h = (const uint4*)Ahi; const uint4* A4l = (const uint4*)Alo;
    const uint4* B4h = (const uint4*)Bhi; const uint4* B4l = (const uint4*)Blo;

    float acc[2][NT][4];
#pragma unroll
    for (int mt = 0; mt < 2; mt++)
#pragma unroll
        for (int nt = 0; nt < NT; nt++)
#pragma unroll
            for (int r = 0; r < 4; r++) acc[mt][nt][r] = 0.f;

    int nCh = K >> 6;
    for (int kc = 0; kc < nCh; kc++) {
        {   // A tile: 128 rows x 64 bf16, 2 threads per row
            int row = tid >> 1, cb = (tid & 1)*4;
            size_t src = ((((size_t)(rowBase + row))*K + kc*64) >> 3) + cb;
#pragma unroll
            for (int j = 0; j < 4; j++) {
                uint32_t sw = swz((uint32_t)(row*128 + (cb + j)*16));
                *(uint4*)(pAh + sw) = A4h[src + j];
                *(uint4*)(pAl + sw) = A4l[src + j];
            }
        }
        // B tile: TN rows x 64 bf16
        for (int idx = tid; idx < TN*8; idx += 256) {
            int n = idx >> 3, j = idx & 7;
            size_t src = ((((size_t)(colBase + n))*K + kc*64) >> 3) + j;
            uint32_t sw = swz((uint32_t)(n*128 + j*16));
            *(uint4*)(pBh + sw) = B4h[src];
            *(uint4*)(pBl + sw) = B4l[src];
        }
        __syncthreads();
#pragma unroll
        for (int ks = 0; ks < 4; ks++) {
            uint32_t ah[2][4], al[2][4], bh[NT][2], bl[NT][2];
#pragma unroll
            for (int mt = 0; mt < 2; mt++) {
                uint32_t off = swz((uint32_t)((wm*32 + mt*16 + (lane & 15))*128
                                              + ks*32 + (lane >> 4)*16));
                LDSM_X4(ah[mt], A_HI + off);
                LDSM_X4(al[mt], A_LO + off);
            }
#pragma unroll
            for (int nt = 0; nt < NT; nt++) {
                uint32_t off = swz((uint32_t)((wn*(TN/2) + nt*8 + (lane & 7))*128
                                              + ks*32 + ((lane >> 3) & 1)*16));
                LDSM_X2(bh[nt], B_HI + off);
                LDSM_X2(bl[nt], B_LO + off);
            }
#pragma unroll
            for (int mt = 0; mt < 2; mt++)
#pragma unroll
                for (int nt = 0; nt < NT; nt++) {
                    mma16816(acc[mt][nt], ah[mt], bh[nt]);
                    mma16816(acc[mt][nt], al[mt], bh[nt]);
                    mma16816(acc[mt][nt], ah[mt], bl[nt]);
                }
        }
        __syncthreads();
    }

    // epilogue: c-frag thread l: rows (l>>2), (l>>2)+8; cols (l&3)*2, +1
#pragma unroll
    for (int mt = 0; mt < 2; mt++) {
#pragma unroll
        for (int nt = 0; nt < NT; nt++) {
#pragma unroll
            for (int half = 0; half < 2; half++) {
                int r = rowBase + wm*32 + mt*16 + (lane >> 2) + half*8;
#pragma unroll
                for (int q = 0; q < 2; q++) {
                    int c = colBase + wn*(TN/2) + nt*8 + (lane & 3)*2 + q;
                    float v = acc[mt][nt][half*2 + q];
                    size_t o = (size_t)r*Nfull + c;
                    if (MODE == 2) {
                        v = fmaxf(v, 0.f); v *= v;
                        __nv_bfloat16 h, l; split_bf(v, h, l);
                        Chi[o] = h; Clo[o] = l;
                    } else {
                        if (MODE == 1) v += R[o];
                        Cf[o] = v;
                    }
                }
            }
        }
    }
}

// ---------------- prelude ----------------
__global__ void k_prelude(const float* __restrict__ x, const float* __restrict__ x0,
                          const float* __restrict__ lam) {
    int n = blockIdx.x, tid = threadIdx.x;
    __shared__ float red[128];
    float l0 = lam[0], l1 = lam[1];
    float v[4]; float ss = 0.f;
#pragma unroll
    for (int r = 0; r < 4; r++) {
        int d = tid + r*128;
        float t = l0*x[n*DIM+d] + l1*x0[n*DIM+d];
        v[r] = t; g_xr[n*DIM+d] = t; ss += t*t;
    }
    red[tid] = ss; __syncthreads();
    for (int s = 64; s > 0; s >>= 1) { if (tid < s) red[tid] += red[tid+s]; __syncthreads(); }
    float rms = rsqrtf(red[0]*(1.f/512.f) + 1e-6f);
#pragma unroll
    for (int r = 0; r < 4; r++) {
        int d = tid + r*128; float t = v[r]*rms;
        g_xn[n*DIM+d] = t;
        __nv_bfloat16 h, l; split_bf(t, h, l);
        g_xnh[n*DIM+d] = h; g_xnl[n*DIM+d] = l;
    }
}

__global__ void k_rmsnorm2() {
    int n = blockIdx.x, tid = threadIdx.x;
    __shared__ float red[128];
    float v[4]; float ss = 0.f;
#pragma unroll
    for (int r = 0; r < 4; r++) { int d = tid + r*128; float t = g_x2[n*DIM+d]; v[r]=t; ss += t*t; }
    red[tid] = ss; __syncthreads();
    for (int s = 64; s > 0; s >>= 1) { if (tid < s) red[tid] += red[tid+s]; __syncthreads(); }
    float rms = rsqrtf(red[0]*(1.f/512.f) + 1e-6f);
#pragma unroll
    for (int r = 0; r < 4; r++) {
        int d = tid + r*128; float t = v[r]*rms;
        __nv_bfloat16 h, l; split_bf(t, h, l);
        g_xnh[n*DIM+d] = h; g_xnl[n*DIM+d] = l;
    }
}

// ---------------- small fp32 sgemm (Wg only) ----------------
__global__ void sgemm(const float* __restrict__ A, const float* __restrict__ B,
                      float* __restrict__ C, int M, int N, int K) {
    __shared__ float As[16][68];
    __shared__ float Bs[16][64];
    int bx = blockIdx.x, by = blockIdx.y;
    int tid = threadIdx.x;
    int tx = tid & 15, ty = tid >> 4;
    int rowBase = by*64, colBase = bx*64;
    float acc[4][4] = {};
    for (int k0 = 0; k0 < K; k0 += 16) {
        {
            int m = tid >> 2, kq = tid & 3;
            float4 av = *(const float4*)(A + (size_t)(rowBase+m)*K + k0 + kq*4);
            As[kq*4+0][m] = av.x; As[kq*4+1][m] = av.y;
            As[kq*4+2][m] = av.z; As[kq*4+3][m] = av.w;
        }
        {
            int kk = tid >> 4, nq = tid & 15;
            int gcb = colBase + nq*4;
            float4 bv;
            if (gcb + 3 < N) bv = *(const float4*)(B + (size_t)(k0+kk)*N + gcb);
            else {
                float t[4] = {0.f,0.f,0.f,0.f};
                for (int q = 0; q < 4; q++) if (gcb+q < N) t[q] = B[(size_t)(k0+kk)*N + gcb+q];
                bv = make_float4(t[0],t[1],t[2],t[3]);
            }
            *(float4*)&Bs[kk][nq*4] = bv;
        }
        __syncthreads();
#pragma unroll
        for (int kk = 0; kk < 16; kk++) {
            float4 a = *(const float4*)&As[kk][ty*4];
            float4 b = *(const float4*)&Bs[kk][tx*4];
            acc[0][0]+=a.x*b.x; acc[0][1]+=a.x*b.y; acc[0][2]+=a.x*b.z; acc[0][3]+=a.x*b.w;
            acc[1][0]+=a.y*b.x; acc[1][1]+=a.y*b.y; acc[1][2]+=a.y*b.z; acc[1][3]+=a.y*b.w;
            acc[2][0]+=a.z*b.x; acc[2][1]+=a.z*b.y; acc[2][2]+=a.z*b.z; acc[2][3]+=a.z*b.w;
            acc[3][0]+=a.w*b.x; acc[3][1]+=a.w*b.y; acc[3][2]+=a.w*b.z; acc[3][3]+=a.w*b.w;
        }
        __syncthreads();
    }
#pragma unroll
    for (int i = 0; i < 4; i++) {
        int r = rowBase + ty*4 + i;
#pragma unroll
        for (int j = 0; j < 4; j++) {
            int c = colBase + tx*4 + j; if (c >= N) continue;
            C[(size_t)r*N + c] = acc[i][j];
        }
    }
}

// ---------------- rope from fused qkv ----------------
__global__ void k_rope() {
    int n = blockIdx.x, h = blockIdx.y, d = threadIdx.x;
    int src = n*1536 + h*64 + d;
    int dst = (h*NN + n)*64 + d;
    g_v[dst] = g_qkv[src + 1024];
    if (d < 32) {
        float inv = expf(-(float)d * (9.210340371976184f/32.f));
        float ang = (float)n * inv;
        float cs = cosf(ang), sn = sinf(ang);
        float a = g_qkv[src], b = g_qkv[src+32];
        g_q[dst]    = a*cs - b*sn;
        g_q[dst+32] = b*cs + a*sn;
        a = g_qkv[src+512]; b = g_qkv[src+512+32];
        g_k[dst]    = a*cs - b*sn;
        g_k[dst+32] = b*cs + a*sn;
    }
}

// ---------------- compressed K/V ----------------
__global__ void k_ckcv(const float* __restrict__ kpos, const float* __restrict__ vpos,
                       const float* __restrict__ Wck, const float* __restrict__ bck,
                       const float* __restrict__ Wcv, const float* __restrict__ bcv,
                       const float* __restrict__ kmem, const float* __restrict__ vmem) {
    __shared__ float kbs[1024], vbs[1024];
    int row = blockIdx.x, h = row >> 6, c = row & 63, tid = threadIdx.x;
    for (int e = tid; e < 1024; e += 64) {
        int j = e >> 6, d = e & 63;
        kbs[e] = g_k[(h*NN + c*16 + j)*64 + d] + kpos[h*1024 + e];
        vbs[e] = g_v[(h*NN + c*16 + j)*64 + d] + vpos[h*1024 + e];
    }
    __syncthreads();
    int d = tid;
    float ak = bck[d], av = bcv[d];
#pragma unroll 4
    for (int e = 0; e < 1024; e++) {
        ak += kbs[e] * Wck[e*64 + d];
        av += vbs[e] * Wcv[e*64 + d];
    }
    g_ckf[(h*65 + 1 + c)*64 + d] = ak;
    g_cvf[(h*65 + 1 + c)*64 + d] = av;
    if (c == 0) {
        g_ckf[h*65*64 + d] = kmem[h*64 + d];
        g_cvf[h*65*64 + d] = vmem[h*64 + d];
    }
}

// ---------------- compressed attention + top-8 ----------------
__global__ void k_compressed() {
    int i = blockIdx.x, h = blockIdx.y, tid = threadIdx.x;
    __shared__ float qs[64], attn[65], red[128];
    __shared__ unsigned long long keys[64], tr[64];
    if (tid < 64) qs[tid] = g_q[(h*NN + i)*64 + tid];
    __syncthreads();
    int own = i >> 4;
    if (tid < 65) {
        float s = NEGF;
        if (tid == 0 || (tid - 1) < own) {
            const float* kr = g_ckf + (h*65 + tid)*64;
            float acc = 0.f;
#pragma unroll
            for (int d = 0; d < 64; d++) acc += qs[d]*kr[d];
            s = acc * SCALE;
        }
        attn[tid] = s;
    }
    __syncthreads();
    red[tid] = (tid < 65) ? attn[tid] : NEGF;
    __syncthreads();
    for (int s = 64; s > 0; s >>= 1) { if (tid < s) red[tid] = fmaxf(red[tid], red[tid+s]); __syncthreads(); }
    float m = red[0]; __syncthreads();
    float e = 0.f;
    if (tid < 65) { e = __expf(attn[tid] - m); attn[tid] = e; }
    red[tid] = e; __syncthreads();
    for (int s = 64; s > 0; s >>= 1) { if (tid < s) red[tid] += red[tid+s]; __syncthreads(); }
    float inv = 1.f / red[0];
    __syncthreads();
    if (tid < 65) attn[tid] *= inv;
    __syncthreads();
    if (tid < 64) {
        float acc = 0.f;
        for (int j = 0; j <= own; j++) acc += attn[j] * g_cvf[(h*65 + j)*64 + tid];
        g_cout[(h*NN + i)*64 + tid] = acc;
    }
    if (tid < 64) {
        unsigned long long kk = 0ULL;
        if (tid < own) {
            unsigned fb = __float_as_uint(attn[1 + tid]);
            kk = ((unsigned long long)fb << 32) | (unsigned)(0xFFFFFFFFu - tid);
        }
        keys[tid] = kk;
    }
    __syncthreads();
    int base = (h*NN + i)*8;
    int nv = 0;
    for (int t = 0; t < 8; t++) {
        if (tid < 64) tr[tid] = keys[tid];
        __syncthreads();
        for (int s = 32; s > 0; s >>= 1) {
            if (tid < s && tr[tid+s] > tr[tid]) tr[tid] = tr[tid+s];
            __syncthreads();
        }
        unsigned long long best = tr[0];
        if (best) {
            int c = (int)(0xFFFFFFFFu - (unsigned)(best & 0xFFFFFFFFu));
            nv = t + 1;
            if (tid == 0) { g_sel[base + t] = c; keys[c] = 0ULL; }
        } else if (tid == 0) g_sel[base + t] = 0;
        __syncthreads();
    }
    if (tid == 0) g_nval[h*NN + i] = nv;
}

// ---------------- fine attention ----------------
__global__ void k_fine() {
    int i = blockIdx.x, h = blockIdx.y, tid = threadIdx.x;
    int w = tid >> 5, lane = tid & 31;
    __shared__ float qs[64], sc[160], red[256], wacc[8][64];
    __shared__ int toks[160];
    if (tid < 64) qs[tid] = g_q[(h*NN + i)*64 + tid];
    int own = i >> 4, nv = g_nval[h*NN + i], base = (h*NN + i)*8;
    int nk = nv*16 + (i & 15) + 1;
    if (tid < nk) {
        int t;
        if (tid < nv*16) t = g_sel[base + (tid >> 4)]*16 + (tid & 15);
        else             t = own*16 + (tid - nv*16);
        toks[tid] = t;
    }
    __syncthreads();
    for (int kk = w; kk < nk; kk += 8) {
        const float* kr = g_k + (h*NN + toks[kk])*64;
        float p = qs[lane]*kr[lane] + qs[lane+32]*kr[lane+32];
#pragma unroll
        for (int o = 16; o > 0; o >>= 1) p += __shfl_down_sync(0xFFFFFFFFu, p, o);
        if (lane == 0) sc[kk] = p * SCALE;
    }
    __syncthreads();
    red[tid] = (tid < nk) ? sc[tid] : NEGF;
    __syncthreads();
    for (int s = 128; s > 0; s >>= 1) { if (tid < s) red[tid] = fmaxf(red[tid], red[tid+s]); __syncthreads(); }
    float m = red[0]; __syncthreads();
    float e = 0.f;
    if (tid < nk) e = __expf(sc[tid] - m);
    red[tid] = e; __syncthreads();
    for (int s = 128; s > 0; s >>= 1) { if (tid < s) red[tid] += red[tid+s]; __syncthreads(); }
    float inv = 1.f / red[0];
    __syncthreads();
    if (tid < nk) sc[tid] = e * inv;
    __syncthreads();
    float a0 = 0.f, a1 = 0.f;
    for (int kk = w; kk < nk; kk += 8) {
        const float* vr = g_v + (h*NN + toks[kk])*64;
        float p = sc[kk];
        a0 += p * vr[lane]; a1 += p * vr[lane+32];
    }
    wacc[w][lane] = a0; wacc[w][lane+32] = a1;
    __syncthreads();
    if (tid < 64) {
        float s = 0.f;
#pragma unroll
        for (int ww = 0; ww < 8; ww++) s += wacc[ww][tid];
        g_fout[(h*NN + i)*64 + tid] = s;
    }
}

// ---------------- sliding window ----------------
__global__ void k_sliding() {
    int qt = blockIdx.x, h = blockIdx.y, tid = threadIdx.x;
    int i0 = qt*16;
    __shared__ float qs[16][65], ks[16][65], vs[16][65], accs[16][64], sc[16][17];
    __shared__ float mrow[16], lrow[16], alpha[16];
#pragma unroll
    for (int r = 0; r < 8; r++) {
        int idx = tid + r*128; int qi = idx >> 6, d = idx & 63;
        qs[qi][d] = g_q[(h*NN + i0 + qi)*64 + d];
        accs[qi][d] = 0.f;
    }
    if (tid < 16) { mrow[tid] = -INFINITY; lrow[tid] = 0.f; }
    __syncthreads();
    int t0 = (qt > 16) ? (qt - 16) : 0;
    for (int t = t0; t <= qt; t++) {
#pragma unroll
        for (int r = 0; r < 8; r++) {
            int idx = tid + r*128; int kj = idx >> 6, d = idx & 63;
            ks[kj][d] = g_k[(h*NN + t*16 + kj)*64 + d];
            vs[kj][d] = g_v[(h*NN + t*16 + kj)*64 + d];
        }
        __syncthreads();
#pragma unroll
        for (int r = 0; r < 2; r++) {
            int p = tid + r*128; int qi = p >> 4, kj = p & 15;
            int j = t*16 + kj, ii = i0 + qi;
            float s = 0.f;
#pragma unroll
            for (int d = 0; d < 64; d++) s += qs[qi][d]*ks[kj][d];
            bool vis = (j <= ii) && (ii - j < 256);
            sc[qi][kj] = vis ? s*SCALE : -INFINITY;
        }
        __syncthreads();
        if (tid < 16) {
            int qi = tid;
            float rm = -INFINITY;
            for (int kj = 0; kj < 16; kj++) rm = fmaxf(rm, sc[qi][kj]);
            float nm = fmaxf(mrow[qi], rm);
            float al, rs = 0.f;
            if (nm == -INFINITY) {
                al = 1.f;
                for (int kj = 0; kj < 16; kj++) sc[qi][kj] = 0.f;
            } else {
                al = __expf(mrow[qi] - nm);
                for (int kj = 0; kj < 16; kj++) {
                    float ee = __expf(sc[qi][kj] - nm);
                    sc[qi][kj] = ee; rs += ee;
                }
            }
            mrow[qi] = nm; alpha[qi] = al; lrow[qi] = lrow[qi]*al + rs;
        }
        __syncthreads();
#pragma unroll
        for (int r = 0; r < 8; r++) {
            int idx = tid + r*128; int qi = idx >> 6, d = idx & 63;
            float a = accs[qi][d]*alpha[qi];
#pragma unroll
            for (int kj = 0; kj < 16; kj++) a += sc[qi][kj]*vs[kj][d];
            accs[qi][d] = a;
        }
        __syncthreads();
    }
#pragma unroll
    for (int r = 0; r < 8; r++) {
        int idx = tid + r*128; int qi = idx >> 6, d = idx & 63;
        g_sout[(h*NN + i0 + qi)*64 + d] = accs[qi][d] / lrow[qi];
    }
}

// ---------------- gated combine -> bf16 hi/lo ----------------
__global__ void k_combine() {
    int n = blockIdx.x, c = threadIdx.x;
    int h = c >> 6, d = c & 63;
    const float* gl = g_gate + n*24 + h*3;
    float g0 = 1.f/(1.f + __expf(-gl[0]));
    float g1 = 1.f/(1.f + __expf(-gl[1]));
    float g2 = 1.f/(1.f + __expf(-gl[2]));
    int idx = (h*NN + n)*64 + d;
    float v = g0*g_cout[idx] + g1*g_fout[idx] + g2*g_sout[idx];
    __nv_bfloat16 hh, ll; split_bf(v, hh, ll);
    g_ohi[n*DIM + c] = hh; g_olo[n*DIM + c] = ll;
}

// ---------------- launch ----------------
extern "C" void kernel_launch(void* const* d_in, const int* in_sizes, int n_in,
                              void* d_out, int out_size) {
    const float* x    = (const float*)d_in[0];
    const float* x0   = (const float*)d_in[2];
    const float* lam  = (const float*)d_in[3];
    const float* Wq   = (const float*)d_in[4];
    const float* Wk   = (const float*)d_in[5];
    const float* Wv   = (const float*)d_in[6];
    const float* Wo   = (const float*)d_in[7];
    const float* Wg   = (const float*)d_in[8];
    const float* kpos = (const float*)d_in[9];
    const float* vpos = (const float*)d_in[10];
    const float* Wck  = (const float*)d_in[11];
    const float* bck  = (const float*)d_in[12];
    const float* Wcv  = (const float*)d_in[13];
    const float* bcv  = (const float*)d_in[14];
    const float* kmem = (const float*)d_in[15];
    const float* vmem = (const float*)d_in[16];
    const float* W1   = (const float*)d_in[17];
    const float* W2   = (const float*)d_in[18];
    float* out = (float*)d_out;

    float *p_xn, *p_xr, *p_gate, *p_x2;
    cudaGetSymbolAddress((void**)&p_xn,  g_xn);
    cudaGetSymbolAddress((void**)&p_xr,  g_xr);
    cudaGetSymbolAddress((void**)&p_gate,g_gate);
    cudaGetSymbolAddress((void**)&p_x2,  g_x2);
    float* p_qkv; cudaGetSymbolAddress((void**)&p_qkv, g_qkv);
    __nv_bfloat16 *p_xnh,*p_xnl,*p_ohi,*p_olo,*p_hhi,*p_hlo;
    __nv_bfloat16 *p_qkvTh,*p_qkvTl,*p_woTh,*p_woTl,*p_w1Th,*p_w1Tl,*p_w2Th,*p_w2Tl;
    cudaGetSymbolAddress((void**)&p_xnh, g_xnh);  cudaGetSymbolAddress((void**)&p_xnl, g_xnl);
    cudaGetSymbolAddress((void**)&p_ohi, g_ohi);  cudaGetSymbolAddress((void**)&p_olo, g_olo);
    cudaGetSymbolAddress((void**)&p_hhi, g_hhi);  cudaGetSymbolAddress((void**)&p_hlo, g_hlo);
    cudaGetSymbolAddress((void**)&p_qkvTh, g_wqkvTh); cudaGetSymbolAddress((void**)&p_qkvTl, g_wqkvTl);
    cudaGetSymbolAddress((void**)&p_woTh, g_woTh);   cudaGetSymbolAddress((void**)&p_woTl, g_woTl);
    cudaGetSymbolAddress((void**)&p_w1Th, g_w1Th);   cudaGetSymbolAddress((void**)&p_w1Tl, g_w1Tl);
    cudaGetSymbolAddress((void**)&p_w2Th, g_w2Th);   cudaGetSymbolAddress((void**)&p_w2Tl, g_w2Tl);

    const int SMB = 49152;  // 128x64 A hi/lo + 64x64 B hi/lo
    cudaFuncSetAttribute(hm_gemm<64,0>, cudaFuncAttributeMaxDynamicSharedMemorySize, SMB);
    cudaFuncSetAttribute(hm_gemm<64,1>, cudaFuncAttributeMaxDynamicSharedMemorySize, SMB);
    cudaFuncSetAttribute(hm_gemm<64,2>, cudaFuncAttributeMaxDynamicSharedMemorySize, SMB);

    // weight conversion (transpose + bf16 split)
    k_convT<<<(512*512+255)/256, 256>>>(Wq, p_qkvTh, p_qkvTl, 512, 512, 0);
    k_convT<<<(512*512+255)/256, 256>>>(Wk, p_qkvTh, p_qkvTl, 512, 512, 512);
    k_convT<<<(512*512+255)/256, 256>>>(Wv, p_qkvTh, p_qkvTl, 512, 512, 1024);
    k_convT<<<(512*512+255)/256, 256>>>(Wo, p_woTh, p_woTl, 512, 512, 0);
    k_convT<<<(512*2048+255)/256, 256>>>(W1, p_w1Th, p_w1Tl, 512, 2048, 0);
    k_convT<<<(2048*512+255)/256, 256>>>(W2, p_w2Th, p_w2Tl, 2048, 512, 0);

    k_prelude<<<NN, 128>>>(x, x0, lam);

    // fused QKV: [1024,512] @ [512,1536]
    hm_gemm<64,0><<<dim3(24,8), 256, SMB>>>(p_xnh, p_xnl, p_qkvTh, p_qkvTl,
                                            nullptr, p_qkv, nullptr, nullptr, 512, 1536);
    sgemm<<<dim3(1,16), 256>>>(p_xn, Wg, p_gate, 1024, 24, 512);

    k_rope<<<dim3(NN, HH), 64>>>();
    k_ckcv<<<HH*CC, 64>>>(kpos, vpos, Wck, bck, Wcv, bcv, kmem, vmem);

    k_compressed<<<dim3(NN, HH), 128>>>();
    k_fine<<<dim3(NN, HH), 256>>>();
    k_sliding<<<dim3(NN/16, HH), 128>>>();
    k_combine<<<NN, 512>>>();

    // x2 = xr + o @ Wo
    hm_gemm<64,1><<<dim3(8,8), 256, SMB>>>(p_ohi, p_olo, p_woTh, p_woTl,
                                           p_xr, p_x2, nullptr, nullptr, 512, 512);
    k_rmsnorm2<<<NN, 128>>>();
    // h = relu(xn2 @ W1)^2 -> bf16 hi/lo
    hm_gemm<64,2><<<dim3(32,8), 256, SMB>>>(p_xnh, p_xnl, p_w1Th, p_w1Tl,
                                            nullptr, nullptr, p_hhi, p_hlo, 512, 2048);
    // out = x2 + h @ W2
    hm_gemm<64,1><<<dim3(8,8), 256, SMB>>>(p_hhi, p_hlo, p_w2Th, p_w2Tl,
                                           p_x2, out, nullptr, nullptr, 2048, 512);
}

// round 8
// speedup vs baseline: 1.8954x; 1.7067x over previous
#include <cuda_runtime.h>
#include <cuda_bf16.h>
#include <stdint.h>
#include <math.h>

#define NN 1024
#define DIM 512
#define HH 8
#define DD 64
#define CC 64
#define SCALE 0.125f
#define NEGF -1e30f

// ---------------- scratch ----------------
__device__ float g_xr [NN*DIM];
__device__ __nv_bfloat16 g_xnh[NN*DIM], g_xnl[NN*DIM];
__device__ float g_qkv[NN*1600];           // q(512) k(512) v(512) gates(24) pad(40)
__device__ float g_q  [HH*NN*DD];
__device__ float g_k  [HH*NN*DD];
__device__ float g_v  [HH*NN*DD];
__device__ float g_ckf[HH*65*DD];
__device__ float g_cvf[HH*65*DD];
__device__ float g_cout[HH*NN*DD];
__device__ float g_fout[HH*NN*DD];
__device__ float g_sout[HH*NN*DD];
__device__ int   g_sel [HH*NN*8];
__device__ int   g_nval[HH*NN];
__device__ __nv_bfloat16 g_ohi[NN*DIM], g_olo[NN*DIM];
__device__ float g_x2 [NN*DIM];
__device__ __nv_bfloat16 g_hhi[NN*2048], g_hlo[NN*2048];
// transposed bf16 hi/lo weights: [Nout][K]
__device__ __nv_bfloat16 g_wqkvTh[1600*512], g_wqkvTl[1600*512];
__device__ __nv_bfloat16 g_woTh[512*512],    g_woTl[512*512];
__device__ __nv_bfloat16 g_w1Th[2048*512],   g_w1Tl[2048*512];
__device__ __nv_bfloat16 g_w2Th[512*2048],   g_w2Tl[512*2048];

// ---------------- helpers ----------------
__device__ __forceinline__ uint32_t smem_u32(const void* p) {
    uint32_t a;
    asm("{ .reg .u64 t; cvta.to.shared.u64 t, %1; cvt.u32.u64 %0, t; }" : "=r"(a) : "l"(p));
    return a;
}
__device__ __forceinline__ uint32_t swz(uint32_t off) { return off ^ ((off >> 3) & 0x70); }

#define LDSM_X4(r, addr) \
    asm volatile("ldmatrix.sync.aligned.m8n8.x4.shared.b16 {%0,%1,%2,%3}, [%4];" \
        : "=r"((r)[0]),"=r"((r)[1]),"=r"((r)[2]),"=r"((r)[3]) : "r"(addr))
#define LDSM_X2(r, addr) \
    asm volatile("ldmatrix.sync.aligned.m8n8.x2.shared.b16 {%0,%1}, [%2];" \
        : "=r"((r)[0]),"=r"((r)[1]) : "r"(addr))
#define CP16(dst, src) \
    asm volatile("cp.async.cg.shared.global [%0], [%1], 16;" :: "r"(dst), "l"(src))
#define CP_COMMIT() asm volatile("cp.async.commit_group;" ::: "memory")
#define CP_WAIT(n)  asm volatile("cp.async.wait_group %0;" :: "n"(n) : "memory")

__device__ __forceinline__ void mma16816(float* d, const uint32_t* a, const uint32_t* b) {
    asm volatile("mma.sync.aligned.m16n8k16.row.col.f32.bf16.bf16.f32 "
        "{%0,%1,%2,%3}, {%4,%5,%6,%7}, {%8,%9}, {%0,%1,%2,%3};"
        : "+f"(d[0]),"+f"(d[1]),"+f"(d[2]),"+f"(d[3])
        : "r"(a[0]),"r"(a[1]),"r"(a[2]),"r"(a[3]), "r"(b[0]),"r"(b[1]));
}
__device__ __forceinline__ void split_bf(float x, __nv_bfloat16& h, __nv_bfloat16& l) {
    h = __float2bfloat16(x);
    l = __float2bfloat16(x - __bfloat162float(h));
}

// ---------------- coalesced weight transpose + split ----------------
// src [K][N] fp32 -> dhi/dlo rows [rowOff+n][k]. Grid (N/32, K/32), block (32,8).
__global__ void k_convT(const float* __restrict__ src, __nv_bfloat16* __restrict__ dhi,
                        __nv_bfloat16* __restrict__ dlo, int K, int N, int rowOff) {
    __shared__ __nv_bfloat16 th[32][33], tl[32][33];
    int tK = blockIdx.y*32, tN = blockIdx.x*32;
    int tx = threadIdx.x, ty = threadIdx.y;
#pragma unroll
    for (int r = 0; r < 4; r++) {
        int k = tK + ty + r*8, n = tN + tx;
        float v = src[(size_t)k*N + n];
        __nv_bfloat16 h, l; split_bf(v, h, l);
        th[ty + r*8][tx] = h; tl[ty + r*8][tx] = l;
    }
    __syncthreads();
#pragma unroll
    for (int r = 0; r < 4; r++) {
        int n = tN + ty + r*8, k = tK + tx;
        size_t o = (size_t)(rowOff + n)*K + k;
        dhi[o] = th[tx][ty + r*8];
        dlo[o] = tl[tx][ty + r*8];
    }
}

// Wg [512][24] -> qkvT rows 1536..1599 (cols >=24 zero). Grid 128, block 256.
__global__ void k_convWg(const float* __restrict__ src) {
    int idx = blockIdx.x*256 + threadIdx.x;   // 64*512 entries
    int n = idx >> 9, k = idx & 511;
    float v = (n < 24) ? src[k*24 + n] : 0.f;
    __nv_bfloat16 h, l; split_bf(v, h, l);
    g_wqkvTh[(size_t)(1536 + n)*512 + k] = h;
    g_wqkvTl[(size_t)(1536 + n)*512 + k] = l;
}

// ---------------- HMMA GEMM with cp.async 2-stage pipeline ----------------
// CTA tile 128 x TN, BK=64. A:[M][K] hi/lo, B:[Nout][K] hi/lo, 3-term split.
// MODE 0: Cf = acc.  MODE 1: Cf = acc + R.  MODE 2: Chi/Clo = split(relu(acc)^2).
template<int TN, int MODE>
__global__ void __launch_bounds__(256)
hm_gemm(const __nv_bfloat16* __restrict__ Ahi, const __nv_bfloat16* __restrict__ Alo,
        const __nv_bfloat16* __restrict__ Bhi, const __nv_bfloat16* __restrict__ Blo,
        const float* __restrict__ R, float* __restrict__ Cf,
        __nv_bfloat16* __restrict__ Chi, __nv_bfloat16* __restrict__ Clo,
        int K, int Nfull) {
    constexpr int NT = TN / 16;
    constexpr int STG = 32768 + 2*TN*128;    // per-stage bytes
    extern __shared__ char dsm[];
    const uint32_t sb = smem_u32(dsm);
    int tid = threadIdx.x, wid = tid >> 5, lane = tid & 31;
    int wm = wid & 3, wn = wid >> 2;
    int rowBase = blockIdx.y*128, colBase = blockIdx.x*TN;

    float acc[2][NT][4];
#pragma unroll
    for (int mt = 0; mt < 2; mt++)
#pragma unroll
        for (int nt = 0; nt < NT; nt++)
#pragma unroll
            for (int r = 0; r < 4; r++) acc[mt][nt][r] = 0.f;

    auto issue = [&](int kc, int s) {
        uint32_t aH = sb + s*STG, aL = aH + 16384, bH = aH + 32768, bL = bH + TN*128;
        int rowL = tid >> 1, cb = (tid & 1)*4;
        const char* sAh = (const char*)(Ahi + ((size_t)(rowBase + rowL))*K + kc*64) + cb*16;
        const char* sAl = (const char*)(Alo + ((size_t)(rowBase + rowL))*K + kc*64) + cb*16;
#pragma unroll
        for (int j = 0; j < 4; j++) {
            uint32_t sw = swz((uint32_t)(rowL*128 + (cb + j)*16));
            CP16(aH + sw, sAh + j*16);
            CP16(aL + sw, sAl + j*16);
        }
#pragma unroll
        for (int it = 0; it < TN*8/256; it++) {
            int idx = tid + it*256;
            int n = idx >> 3, j = idx & 7;
            const char* sBh = (const char*)(Bhi + ((size_t)(colBase + n))*K + kc*64) + j*16;
            const char* sBl = (const char*)(Blo + ((size_t)(colBase + n))*K + kc*64) + j*16;
            uint32_t sw = swz((uint32_t)(n*128 + j*16));
            CP16(bH + sw, sBh);
            CP16(bL + sw, sBl);
        }
    };
    auto compute = [&](int s) {
        uint32_t A_H = sb + s*STG, A_L = A_H + 16384, B_H = A_H + 32768, B_L = B_H + TN*128;
#pragma unroll
        for (int ks = 0; ks < 4; ks++) {
            uint32_t ah[2][4], al[2][4], bh[NT][2], bl[NT][2];
#pragma unroll
            for (int mt = 0; mt < 2; mt++) {
                uint32_t off = swz((uint32_t)((wm*32 + mt*16 + (lane & 15))*128
                                              + ks*32 + (lane >> 4)*16));
                LDSM_X4(ah[mt], A_H + off);
                LDSM_X4(al[mt], A_L + off);
            }
#pragma unroll
            for (int nt = 0; nt < NT; nt++) {
                uint32_t off = swz((uint32_t)((wn*(TN/2) + nt*8 + (lane & 7))*128
                                              + ks*32 + ((lane >> 3) & 1)*16));
                LDSM_X2(bh[nt], B_H + off);
                LDSM_X2(bl[nt], B_L + off);
            }
#pragma unroll
            for (int mt = 0; mt < 2; mt++)
#pragma unroll
                for (int nt = 0; nt < NT; nt++) {
                    mma16816(acc[mt][nt], ah[mt], bh[nt]);
                    mma16816(acc[mt][nt], al[mt], bh[nt]);
                    mma16816(acc[mt][nt], ah[mt], bl[nt]);
                }
        }
    };

    int nCh = K >> 6;
    issue(0, 0); CP_COMMIT();
    for (int kc = 0; kc < nCh; kc++) {
        if (kc + 1 < nCh) { issue(kc + 1, (kc + 1) & 1); CP_COMMIT(); CP_WAIT(1); }
        else CP_WAIT(0);
        __syncthreads();
        compute(kc & 1);
        __syncthreads();
    }

#pragma unroll
    for (int mt = 0; mt < 2; mt++) {
#pragma unroll
        for (int nt = 0; nt < NT; nt++) {
#pragma unroll
            for (int half = 0; half < 2; half++) {
                int r = rowBase + wm*32 + mt*16 + (lane >> 2) + half*8;
#pragma unroll
                for (int q = 0; q < 2; q++) {
                    int c = colBase + wn*(TN/2) + nt*8 + (lane & 3)*2 + q;
                    float v = acc[mt][nt][half*2 + q];
                    size_t o = (size_t)r*Nfull + c;
                    if (MODE == 2) {
                        v = fmaxf(v, 0.f); v *= v;
                        __nv_bfloat16 h, l; split_bf(v, h, l);
                        Chi[o] = h; Clo[o] = l;
                    } else {
                        if (MODE == 1) v += R[o];
                        Cf[o] = v;
                    }
                }
            }
        }
    }
}

// ---------------- prelude ----------------
__global__ void k_prelude(const float* __restrict__ x, const float* __restrict__ x0,
                          const float* __restrict__ lam) {
    int n = blockIdx.x, tid = threadIdx.x;
    __shared__ float red[128];
    float l0 = lam[0], l1 = lam[1];
    float v[4]; float ss = 0.f;
#pragma unroll
    for (int r = 0; r < 4; r++) {
        int d = tid + r*128;
        float t = l0*x[n*DIM+d] + l1*x0[n*DIM+d];
        v[r] = t; g_xr[n*DIM+d] = t; ss += t*t;
    }
    red[tid] = ss; __syncthreads();
    for (int s = 64; s > 0; s >>= 1) { if (tid < s) red[tid] += red[tid+s]; __syncthreads(); }
    float rms = rsqrtf(red[0]*(1.f/512.f) + 1e-6f);
#pragma unroll
    for (int r = 0; r < 4; r++) {
        int d = tid + r*128; float t = v[r]*rms;
        __nv_bfloat16 h, l; split_bf(t, h, l);
        g_xnh[n*DIM+d] = h; g_xnl[n*DIM+d] = l;
    }
}

__global__ void k_rmsnorm2() {
    int n = blockIdx.x, tid = threadIdx.x;
    __shared__ float red[128];
    float v[4]; float ss = 0.f;
#pragma unroll
    for (int r = 0; r < 4; r++) { int d = tid + r*128; float t = g_x2[n*DIM+d]; v[r]=t; ss += t*t; }
    red[tid] = ss; __syncthreads();
    for (int s = 64; s > 0; s >>= 1) { if (tid < s) red[tid] += red[tid+s]; __syncthreads(); }
    float rms = rsqrtf(red[0]*(1.f/512.f) + 1e-6f);
#pragma unroll
    for (int r = 0; r < 4; r++) {
        int d = tid + r*128; float t = v[r]*rms;
        __nv_bfloat16 h, l; split_bf(t, h, l);
        g_xnh[n*DIM+d] = h; g_xnl[n*DIM+d] = l;
    }
}

// ---------------- rope from fused qkv (stride 1600) ----------------
__global__ void k_rope() {
    int n = blockIdx.x, h = blockIdx.y, d = threadIdx.x;
    int src = n*1600 + h*64 + d;
    int dst = (h*NN + n)*64 + d;
    g_v[dst] = g_qkv[src + 1024];
    if (d < 32) {
        float inv = expf(-(float)d * (9.210340371976184f/32.f));
        float ang = (float)n * inv;
        float cs = cosf(ang), sn = sinf(ang);
        float a = g_qkv[src], b = g_qkv[src+32];
        g_q[dst]    = a*cs - b*sn;
        g_q[dst+32] = b*cs + a*sn;
        a = g_qkv[src+512]; b = g_qkv[src+512+32];
        g_k[dst]    = a*cs - b*sn;
        g_k[dst+32] = b*cs + a*sn;
    }
}

// ---------------- compressed K/V (256 threads, 4-way K split) ----------------
__global__ void k_ckcv(const float* __restrict__ kpos, const float* __restrict__ vpos,
                       const float* __restrict__ Wck, const float* __restrict__ bck,
                       const float* __restrict__ Wcv, const float* __restrict__ bcv,
                       const float* __restrict__ kmem, const float* __restrict__ vmem) {
    __shared__ float kbs[1024], vbs[1024];
    __shared__ float redk[4][64], redv[4][64];
    int row = blockIdx.x, h = row >> 6, c = row & 63, tid = threadIdx.x;
    for (int e = tid; e < 1024; e += 256) {
        int j = e >> 6, d = e & 63;
        kbs[e] = g_k[(h*NN + c*16 + j)*64 + d] + kpos[h*1024 + e];
        vbs[e] = g_v[(h*NN + c*16 + j)*64 + d] + vpos[h*1024 + e];
    }
    __syncthreads();
    int part = tid >> 6, d = tid & 63;
    float ak = 0.f, av = 0.f;
    int e0 = part*256;
#pragma unroll 4
    for (int e = e0; e < e0 + 256; e++) {
        ak += kbs[e] * Wck[e*64 + d];
        av += vbs[e] * Wcv[e*64 + d];
    }
    redk[part][d] = ak; redv[part][d] = av;
    __syncthreads();
    if (tid < 64) {
        float sk = bck[tid] + redk[0][tid] + redk[1][tid] + redk[2][tid] + redk[3][tid];
        float sv = bcv[tid] + redv[0][tid] + redv[1][tid] + redv[2][tid] + redv[3][tid];
        g_ckf[(h*65 + 1 + c)*64 + tid] = sk;
        g_cvf[(h*65 + 1 + c)*64 + tid] = sv;
        if (c == 0) {
            g_ckf[h*65*64 + tid] = kmem[h*64 + tid];
            g_cvf[h*65*64 + tid] = vmem[h*64 + tid];
        }
    }
}

// ---------------- compressed attention + top-8 (warp per query) ----------------
__global__ void __launch_bounds__(256) k_compressed() {
    __shared__ float qs[8][64];
    __shared__ float sc[8][72];
    int w = threadIdx.x >> 5, lane = threadIdx.x & 31;
    int i = blockIdx.x*8 + w, h = blockIdx.y;
    int own = i >> 4;
    const float* qp = g_q + (h*NN + i)*64;
    float q0 = qp[lane], q1 = qp[lane + 32];
    qs[w][lane] = q0; qs[w][lane + 32] = q1;
    __syncwarp();
    // scores: lane-per-key float4 dots
    const float4* q4 = (const float4*)qs[w];
    for (int j = lane; j <= own; j += 32) {
        const float4* kr = (const float4*)(g_ckf + (h*65 + j)*64);
        float acc = 0.f;
#pragma unroll
        for (int d4 = 0; d4 < 16; d4++) {
            float4 kv = kr[d4]; float4 qv = q4[d4];
            acc += qv.x*kv.x + qv.y*kv.y + qv.z*kv.z + qv.w*kv.w;
        }
        sc[w][j] = acc * SCALE;
    }
    __syncwarp();
    // warp softmax over 0..own
    float m = -INFINITY;
    for (int j = lane; j <= own; j += 32) m = fmaxf(m, sc[w][j]);
#pragma unroll
    for (int o = 16; o > 0; o >>= 1) m = fmaxf(m, __shfl_xor_sync(0xFFFFFFFFu, m, o));
    float s = 0.f;
    for (int j = lane; j <= own; j += 32) { float e = __expf(sc[w][j] - m); sc[w][j] = e; s += e; }
#pragma unroll
    for (int o = 16; o > 0; o >>= 1) s += __shfl_xor_sync(0xFFFFFFFFu, s, o);
    float inv = 1.f / s;
    __syncwarp();
    // values (warp per key, serial j, MLP-friendly)
    float a0 = 0.f, a1 = 0.f;
    for (int j = 0; j <= own; j++) {
        float a = sc[w][j] * inv;
        const float* vr = g_cvf + (h*65 + j)*64;
        a0 += a * vr[lane]; a1 += a * vr[lane + 32];
    }
    g_cout[(h*NN + i)*64 + lane] = a0;
    g_cout[(h*NN + i)*64 + lane + 32] = a1;
    // top-8 over blocks c in [0, own): value desc, index asc (warp-local)
    unsigned long long k0 = 0ULL, k1 = 0ULL;
    if (lane < own)
        k0 = ((unsigned long long)__float_as_uint(sc[w][1 + lane]) << 32)
           | (unsigned)(0xFFFFFFFFu - lane);
    if (lane + 32 < own)
        k1 = ((unsigned long long)__float_as_uint(sc[w][1 + lane + 32]) << 32)
           | (unsigned)(0xFFFFFFFFu - (lane + 32));
    int base = (h*NN + i)*8, nv = 0;
#pragma unroll
    for (int t = 0; t < 8; t++) {
        unsigned long long mk = (k0 > k1) ? k0 : k1;
#pragma unroll
        for (int o = 16; o > 0; o >>= 1) {
            unsigned long long other = __shfl_xor_sync(0xFFFFFFFFu, mk, o);
            if (other > mk) mk = other;
        }
        if (mk) {
            int c = (int)(0xFFFFFFFFu - (unsigned)(mk & 0xFFFFFFFFu));
            if (k0 == mk) k0 = 0ULL;
            if (k1 == mk) k1 = 0ULL;
            if (lane == 0) g_sel[base + t] = c;
            nv = t + 1;
        } else if (lane == 0) g_sel[base + t] = 0;
    }
    if (lane == 0) g_nval[h*NN + i] = nv;
}

// ---------------- fine attention (warp per query) ----------------
__global__ void __launch_bounds__(256) k_fine() {
    __shared__ float qs[8][64];
    __shared__ float sc[8][160];
    __shared__ int selS[8][8];
    int w = threadIdx.x >> 5, lane = threadIdx.x & 31;
    int i = blockIdx.x*8 + w, h = blockIdx.y;
    int own = i >> 4, nv = g_nval[h*NN + i], base = (h*NN + i)*8;
    int nk = nv*16 + (i & 15) + 1;
    const float* qp = g_q + (h*NN + i)*64;
    float q0 = qp[lane], q1 = qp[lane + 32];
    qs[w][lane] = q0; qs[w][lane + 32] = q1;
    if (lane < 8) selS[w][lane] = g_sel[base + lane];
    __syncwarp();
    // scores: lane-per-key
    const float4* q4 = (const float4*)qs[w];
    for (int kk = lane; kk < nk; kk += 32) {
        int tok = (kk < nv*16) ? selS[w][kk >> 4]*16 + (kk & 15) : own*16 + (kk - nv*16);
        const float4* kr = (const float4*)(g_k + (h*NN + tok)*64);
        float acc = 0.f;
#pragma unroll
        for (int d4 = 0; d4 < 16; d4++) {
            float4 kv = kr[d4]; float4 qv = q4[d4];
            acc += qv.x*kv.x + qv.y*kv.y + qv.z*kv.z + qv.w*kv.w;
        }
        sc[w][kk] = acc * SCALE;
    }
    __syncwarp();
    // warp softmax
    float m = -INFINITY;
    for (int kk = lane; kk < nk; kk += 32) m = fmaxf(m, sc[w][kk]);
#pragma unroll
    for (int o = 16; o > 0; o >>= 1) m = fmaxf(m, __shfl_xor_sync(0xFFFFFFFFu, m, o));
    float s = 0.f;
    for (int kk = lane; kk < nk; kk += 32) { float e = __expf(sc[w][kk] - m); sc[w][kk] = e; s += e; }
#pragma unroll
    for (int o = 16; o > 0; o >>= 1) s += __shfl_xor_sync(0xFFFFFFFFu, s, o);
    float inv = 1.f / s;
    __syncwarp();
    // values: warp per key
    float a0 = 0.f, a1 = 0.f;
    for (int kk = 0; kk < nk; kk++) {
        int tok = (kk < nv*16) ? selS[w][kk >> 4]*16 + (kk & 15) : own*16 + (kk - nv*16);
        float a = sc[w][kk] * inv;
        const float* vr = g_v + (h*NN + tok)*64;
        a0 += a * vr[lane]; a1 += a * vr[lane + 32];
    }
    g_fout[(h*NN + i)*64 + lane] = a0;
    g_fout[(h*NN + i)*64 + lane + 32] = a1;
}

// ---------------- sliding window ----------------
__global__ void k_sliding() {
    int qt = blockIdx.x, h = blockIdx.y, tid = threadIdx.x;
    int i0 = qt*16;
    __shared__ float qs[16][65], ks[16][65], vs[16][65], accs[16][64], sc[16][17];
    __shared__ float mrow[16], lrow[16], alpha[16];
#pragma unroll
    for (int r = 0; r < 8; r++) {
        int idx = tid + r*128; int qi = idx >> 6, d = idx & 63;
        qs[qi][d] = g_q[(h*NN + i0 + qi)*64 + d];
        accs[qi][d] = 0.f;
    }
    if (tid < 16) { mrow[tid] = -INFINITY; lrow[tid] = 0.f; }
    __syncthreads();
    int t0 = (qt > 16) ? (qt - 16) : 0;
    for (int t = t0; t <= qt; t++) {
#pragma unroll
        for (int r = 0; r < 8; r++) {
            int idx = tid + r*128; int kj = idx >> 6, d = idx & 63;
            ks[kj][d] = g_k[(h*NN + t*16 + kj)*64 + d];
            vs[kj][d] = g_v[(h*NN + t*16 + kj)*64 + d];
        }
        __syncthreads();
#pragma unroll
        for (int r = 0; r < 2; r++) {
            int p = tid + r*128; int qi = p >> 4, kj = p & 15;
            int j = t*16 + kj, ii = i0 + qi;
            float s = 0.f;
#pragma unroll
            for (int d = 0; d < 64; d++) s += qs[qi][d]*ks[kj][d];
            bool vis = (j <= ii) && (ii - j < 256);
            sc[qi][kj] = vis ? s*SCALE : -INFINITY;
        }
        __syncthreads();
        if (tid < 16) {
            int qi = tid;
            float rm = -INFINITY;
            for (int kj = 0; kj < 16; kj++) rm = fmaxf(rm, sc[qi][kj]);
            float nm = fmaxf(mrow[qi], rm);
            float al, rs = 0.f;
            if (nm == -INFINITY) {
                al = 1.f;
                for (int kj = 0; kj < 16; kj++) sc[qi][kj] = 0.f;
            } else {
                al = __expf(mrow[qi] - nm);
                for (int kj = 0; kj < 16; kj++) {
                    float ee = __expf(sc[qi][kj] - nm);
                    sc[qi][kj] = ee; rs += ee;
                }
            }
            mrow[qi] = nm; alpha[qi] = al; lrow[qi] = lrow[qi]*al + rs;
        }
        __syncthreads();
#pragma unroll
        for (int r = 0; r < 8; r++) {
            int idx = tid + r*128; int qi = idx >> 6, d = idx & 63;
            float a = accs[qi][d]*alpha[qi];
#pragma unroll
            for (int kj = 0; kj < 16; kj++) a += sc[qi][kj]*vs[kj][d];
            accs[qi][d] = a;
        }
        __syncthreads();
    }
#pragma unroll
    for (int r = 0; r < 8; r++) {
        int idx = tid + r*128; int qi = idx >> 6, d = idx & 63;
        g_sout[(h*NN + i0 + qi)*64 + d] = accs[qi][d] / lrow[qi];
    }
}

// ---------------- gated combine -> bf16 hi/lo (gates from fused qkv) ----------------
__global__ void k_combine() {
    int n = blockIdx.x, c = threadIdx.x;
    int h = c >> 6, d = c & 63;
    const float* gl = g_qkv + n*1600 + 1536 + h*3;
    float g0 = 1.f/(1.f + __expf(-gl[0]));
    float g1 = 1.f/(1.f + __expf(-gl[1]));
    float g2 = 1.f/(1.f + __expf(-gl[2]));
    int idx = (h*NN + n)*64 + d;
    float v = g0*g_cout[idx] + g1*g_fout[idx] + g2*g_sout[idx];
    __nv_bfloat16 hh, ll; split_bf(v, hh, ll);
    g_ohi[n*DIM + c] = hh; g_olo[n*DIM + c] = ll;
}

// ---------------- launch ----------------
extern "C" void kernel_launch(void* const* d_in, const int* in_sizes, int n_in,
                              void* d_out, int out_size) {
    const float* x    = (const float*)d_in[0];
    const float* x0   = (const float*)d_in[2];
    const float* lam  = (const float*)d_in[3];
    const float* Wq   = (const float*)d_in[4];
    const float* Wk   = (const float*)d_in[5];
    const float* Wv   = (const float*)d_in[6];
    const float* Wo   = (const float*)d_in[7];
    const float* Wg   = (const float*)d_in[8];
    const float* kpos = (const float*)d_in[9];
    const float* vpos = (const float*)d_in[10];
    const float* Wck  = (const float*)d_in[11];
    const float* bck  = (const float*)d_in[12];
    const float* Wcv  = (const float*)d_in[13];
    const float* bcv  = (const float*)d_in[14];
    const float* kmem = (const float*)d_in[15];
    const float* vmem = (const float*)d_in[16];
    const float* W1   = (const float*)d_in[17];
    const float* W2   = (const float*)d_in[18];
    float* out = (float*)d_out;

    float *p_xr, *p_x2, *p_qkv;
    cudaGetSymbolAddress((void**)&p_xr,  g_xr);
    cudaGetSymbolAddress((void**)&p_x2,  g_x2);
    cudaGetSymbolAddress((void**)&p_qkv, g_qkv);
    __nv_bfloat16 *p_xnh,*p_xnl,*p_ohi,*p_olo,*p_hhi,*p_hlo;
    __nv_bfloat16 *p_qkvTh,*p_qkvTl,*p_woTh,*p_woTl,*p_w1Th,*p_w1Tl,*p_w2Th,*p_w2Tl;
    cudaGetSymbolAddress((void**)&p_xnh, g_xnh);  cudaGetSymbolAddress((void**)&p_xnl, g_xnl);
    cudaGetSymbolAddress((void**)&p_ohi, g_ohi);  cudaGetSymbolAddress((void**)&p_olo, g_olo);
    cudaGetSymbolAddress((void**)&p_hhi, g_hhi);  cudaGetSymbolAddress((void**)&p_hlo, g_hlo);
    cudaGetSymbolAddress((void**)&p_qkvTh, g_wqkvTh); cudaGetSymbolAddress((void**)&p_qkvTl, g_wqkvTl);
    cudaGetSymbolAddress((void**)&p_woTh, g_woTh);   cudaGetSymbolAddress((void**)&p_woTl, g_woTl);
    cudaGetSymbolAddress((void**)&p_w1Th, g_w1Th);   cudaGetSymbolAddress((void**)&p_w1Tl, g_w1Tl);
    cudaGetSymbolAddress((void**)&p_w2Th, g_w2Th);   cudaGetSymbolAddress((void**)&p_w2Tl, g_w2Tl);

    const int SMB = 2*(32768 + 2*64*128);   // 98304: two pipeline stages
    cudaFuncSetAttribute(hm_gemm<64,0>, cudaFuncAttributeMaxDynamicSharedMemorySize, SMB);
    cudaFuncSetAttribute(hm_gemm<64,1>, cudaFuncAttributeMaxDynamicSharedMemorySize, SMB);
    cudaFuncSetAttribute(hm_gemm<64,2>, cudaFuncAttributeMaxDynamicSharedMemorySize, SMB);

    dim3 cb(32, 8);
    k_convT<<<dim3(16,16), cb>>>(Wq, p_qkvTh, p_qkvTl, 512, 512, 0);
    k_convT<<<dim3(16,16), cb>>>(Wk, p_qkvTh, p_qkvTl, 512, 512, 512);
    k_convT<<<dim3(16,16), cb>>>(Wv, p_qkvTh, p_qkvTl, 512, 512, 1024);
    k_convWg<<<128, 256>>>(Wg);
    k_convT<<<dim3(16,16), cb>>>(Wo, p_woTh, p_woTl, 512, 512, 0);
    k_convT<<<dim3(64,16), cb>>>(W1, p_w1Th, p_w1Tl, 512, 2048, 0);
    k_convT<<<dim3(16,64), cb>>>(W2, p_w2Th, p_w2Tl, 2048, 512, 0);

    k_prelude<<<NN, 128>>>(x, x0, lam);

    // fused QKV+gates: [1024,512] @ [512,1600]
    hm_gemm<64,0><<<dim3(25,8), 256, SMB>>>(p_xnh, p_xnl, p_qkvTh, p_qkvTl,
                                            nullptr, p_qkv, nullptr, nullptr, 512, 1600);

    k_rope<<<dim3(NN, HH), 64>>>();
    k_ckcv<<<HH*CC, 256>>>(kpos, vpos, Wck, bck, Wcv, bcv, kmem, vmem);

    k_compressed<<<dim3(NN/8, HH), 256>>>();
    k_fine<<<dim3(NN/8, HH), 256>>>();
    k_sliding<<<dim3(NN/16, HH), 128>>>();
    k_combine<<<NN, 512>>>();

    // x2 = xr + o @ Wo
    hm_gemm<64,1><<<dim3(8,8), 256, SMB>>>(p_ohi, p_olo, p_woTh, p_woTl,
                                           p_xr, p_x2, nullptr, nullptr, 512, 512);
    k_rmsnorm2<<<NN, 128>>>();
    // h = relu(xn2 @ W1)^2 -> bf16 hi/lo
    hm_gemm<64,2><<<dim3(32,8), 256, SMB>>>(p_xnh, p_xnl, p_w1Th, p_w1Tl,
                                            nullptr, nullptr, p_hhi, p_hlo, 512, 2048);
    // out = x2 + h @ W2
    hm_gemm<64,1><<<dim3(8,8), 256, SMB>>>(p_hhi, p_hlo, p_w2Th, p_w2Tl,
                                           p_x2, out, nullptr, nullptr, 2048, 512);
}

// round 9
// speedup vs baseline: 1.9569x; 1.0324x over previous
#include <cuda_runtime.h>
#include <cuda_bf16.h>
#include <stdint.h>
#include <math.h>

#define NN 1024
#define DIM 512
#define HH 8
#define DD 64
#define CC 64
#define SCALE 0.125f
#define NEGF -1e30f

// ---------------- scratch ----------------
__device__ float g_xr [NN*DIM];
__device__ __nv_bfloat16 g_xnh[NN*DIM], g_xnl[NN*DIM];
__device__ float g_qkv[NN*1600];           // q(512) k(512) v(512) gates(24) pad(40)
__device__ float g_q  [HH*NN*DD];
__device__ float g_k  [HH*NN*DD];
__device__ float g_v  [HH*NN*DD];
__device__ float g_ckf[HH*65*DD];
__device__ float g_cvf[HH*65*DD];
__device__ float g_cout[HH*NN*DD];
__device__ float g_fout[HH*NN*DD];
__device__ float g_sout[HH*NN*DD];
__device__ int   g_sel [HH*NN*8];
__device__ int   g_nval[HH*NN];
__device__ __nv_bfloat16 g_ohi[NN*DIM], g_olo[NN*DIM];
__device__ float g_x2 [NN*DIM];
__device__ __nv_bfloat16 g_hhi[NN*2048], g_hlo[NN*2048];
// transposed bf16 hi/lo weights: [Nout][K]
__device__ __nv_bfloat16 g_wqkvTh[1600*512], g_wqkvTl[1600*512];
__device__ __nv_bfloat16 g_woTh[512*512],    g_woTl[512*512];
__device__ __nv_bfloat16 g_w1Th[2048*512],   g_w1Tl[2048*512];
__device__ __nv_bfloat16 g_w2Th[512*2048],   g_w2Tl[512*2048];

// ---------------- helpers ----------------
__device__ __forceinline__ uint32_t smem_u32(const void* p) {
    uint32_t a;
    asm("{ .reg .u64 t; cvta.to.shared.u64 t, %1; cvt.u32.u64 %0, t; }" : "=r"(a) : "l"(p));
    return a;
}
__device__ __forceinline__ uint32_t swz(uint32_t off) { return off ^ ((off >> 3) & 0x70); }

#define LDSM_X4(r, addr) \
    asm volatile("ldmatrix.sync.aligned.m8n8.x4.shared.b16 {%0,%1,%2,%3}, [%4];" \
        : "=r"((r)[0]),"=r"((r)[1]),"=r"((r)[2]),"=r"((r)[3]) : "r"(addr))
#define LDSM_X2(r, addr) \
    asm volatile("ldmatrix.sync.aligned.m8n8.x2.shared.b16 {%0,%1}, [%2];" \
        : "=r"((r)[0]),"=r"((r)[1]) : "r"(addr))
#define CP16(dst, src) \
    asm volatile("cp.async.cg.shared.global [%0], [%1], 16;" :: "r"(dst), "l"(src))
#define CP_COMMIT() asm volatile("cp.async.commit_group;" ::: "memory")
#define CP_WAIT(n)  asm volatile("cp.async.wait_group %0;" :: "n"(n) : "memory")

__device__ __forceinline__ void mma16816(float* d, const uint32_t* a, const uint32_t* b) {
    asm volatile("mma.sync.aligned.m16n8k16.row.col.f32.bf16.bf16.f32 "
        "{%0,%1,%2,%3}, {%4,%5,%6,%7}, {%8,%9}, {%0,%1,%2,%3};"
        : "+f"(d[0]),"+f"(d[1]),"+f"(d[2]),"+f"(d[3])
        : "r"(a[0]),"r"(a[1]),"r"(a[2]),"r"(a[3]), "r"(b[0]),"r"(b[1]));
}
__device__ __forceinline__ void split_bf(float x, __nv_bfloat16& h, __nv_bfloat16& l) {
    h = __float2bfloat16(x);
    l = __float2bfloat16(x - __bfloat162float(h));
}

// ---------------- ONE fused weight transpose+split kernel ----------------
// tiles: [0,1024) Wq/Wk/Wv/Wo (256 each), [1024,2048) W1, [2048,3072) W2, [3072,3104) Wg
__global__ void k_convAll(const float* __restrict__ Wq, const float* __restrict__ Wk,
                          const float* __restrict__ Wv, const float* __restrict__ Wo,
                          const float* __restrict__ W1, const float* __restrict__ W2,
                          const float* __restrict__ Wg) {
    __shared__ __nv_bfloat16 th[32][33], tl[32][33];
    int t = blockIdx.x;
    const float* src; __nv_bfloat16 *dh, *dl;
    int K, N, rowOff; bool wg = false;
    if (t < 1024) {
        int s = t >> 8; t &= 255; K = 512; N = 512;
        if (s == 0)      { src = Wq; dh = g_wqkvTh; dl = g_wqkvTl; rowOff = 0; }
        else if (s == 1) { src = Wk; dh = g_wqkvTh; dl = g_wqkvTl; rowOff = 512; }
        else if (s == 2) { src = Wv; dh = g_wqkvTh; dl = g_wqkvTl; rowOff = 1024; }
        else             { src = Wo; dh = g_woTh;   dl = g_woTl;   rowOff = 0; }
    } else if (t < 2048) { t -= 1024; src = W1; dh = g_w1Th; dl = g_w1Tl; K = 512;  N = 2048; rowOff = 0; }
    else if (t < 3072)   { t -= 2048; src = W2; dh = g_w2Th; dl = g_w2Tl; K = 2048; N = 512;  rowOff = 0; }
    else { t -= 3072; src = Wg; dh = g_wqkvTh; dl = g_wqkvTl; K = 512; N = 64; rowOff = 1536; wg = true; }
    int tilesN = N >> 5;
    int tN = (t % tilesN)*32, tK = (t / tilesN)*32;
    int tx = threadIdx.x, ty = threadIdx.y;
#pragma unroll
    for (int r = 0; r < 4; r++) {
        int k = tK + ty + r*8, n = tN + tx;
        float v;
        if (wg) v = (n < 24) ? src[(size_t)k*24 + n] : 0.f;
        else    v = src[(size_t)k*N + n];
        __nv_bfloat16 h, l; split_bf(v, h, l);
        th[ty + r*8][tx] = h; tl[ty + r*8][tx] = l;
    }
    __syncthreads();
#pragma unroll
    for (int r = 0; r < 4; r++) {
        int n = tN + ty + r*8, k = tK + tx;
        size_t o = (size_t)(rowOff + n)*K + k;
        dh[o] = th[tx][ty + r*8];
        dl[o] = tl[tx][ty + r*8];
    }
}

// ---------------- HMMA GEMM with cp.async 2-stage pipeline ----------------
template<int TN, int MODE>
__global__ void __launch_bounds__(256, 2)
hm_gemm(const __nv_bfloat16* __restrict__ Ahi, const __nv_bfloat16* __restrict__ Alo,
        const __nv_bfloat16* __restrict__ Bhi, const __nv_bfloat16* __restrict__ Blo,
        const float* __restrict__ R, float* __restrict__ Cf,
        __nv_bfloat16* __restrict__ Chi, __nv_bfloat16* __restrict__ Clo,
        int K, int Nfull) {
    constexpr int NT = TN / 16;
    constexpr int STG = 32768 + 2*TN*128;
    extern __shared__ char dsm[];
    const uint32_t sb = smem_u32(dsm);
    int tid = threadIdx.x, wid = tid >> 5, lane = tid & 31;
    int wm = wid & 3, wn = wid >> 2;
    int rowBase = blockIdx.y*128, colBase = blockIdx.x*TN;

    float acc[2][NT][4];
#pragma unroll
    for (int mt = 0; mt < 2; mt++)
#pragma unroll
        for (int nt = 0; nt < NT; nt++)
#pragma unroll
            for (int r = 0; r < 4; r++) acc[mt][nt][r] = 0.f;

    auto issue = [&](int kc, int s) {
        uint32_t aH = sb + s*STG, aL = aH + 16384, bH = aH + 32768, bL = bH + TN*128;
        int rowL = tid >> 1, cb = (tid & 1)*4;
        const char* sAh = (const char*)(Ahi + ((size_t)(rowBase + rowL))*K + kc*64) + cb*16;
        const char* sAl = (const char*)(Alo + ((size_t)(rowBase + rowL))*K + kc*64) + cb*16;
#pragma unroll
        for (int j = 0; j < 4; j++) {
            uint32_t sw = swz((uint32_t)(rowL*128 + (cb + j)*16));
            CP16(aH + sw, sAh + j*16);
            CP16(aL + sw, sAl + j*16);
        }
#pragma unroll
        for (int it = 0; it < TN*8/256; it++) {
            int idx = tid + it*256;
            int n = idx >> 3, j = idx & 7;
            const char* sBh = (const char*)(Bhi + ((size_t)(colBase + n))*K + kc*64) + j*16;
            const char* sBl = (const char*)(Blo + ((size_t)(colBase + n))*K + kc*64) + j*16;
            uint32_t sw = swz((uint32_t)(n*128 + j*16));
            CP16(bH + sw, sBh);
            CP16(bL + sw, sBl);
        }
    };
    auto compute = [&](int s) {
        uint32_t A_H = sb + s*STG, A_L = A_H + 16384, B_H = A_H + 32768, B_L = B_H + TN*128;
#pragma unroll
        for (int ks = 0; ks < 4; ks++) {
            uint32_t ah[2][4], al[2][4], bh[NT][2], bl[NT][2];
#pragma unroll
            for (int mt = 0; mt < 2; mt++) {
                uint32_t off = swz((uint32_t)((wm*32 + mt*16 + (lane & 15))*128
                                              + ks*32 + (lane >> 4)*16));
                LDSM_X4(ah[mt], A_H + off);
                LDSM_X4(al[mt], A_L + off);
            }
#pragma unroll
            for (int nt = 0; nt < NT; nt++) {
                uint32_t off = swz((uint32_t)((wn*(TN/2) + nt*8 + (lane & 7))*128
                                              + ks*32 + ((lane >> 3) & 1)*16));
                LDSM_X2(bh[nt], B_H + off);
                LDSM_X2(bl[nt], B_L + off);
            }
#pragma unroll
            for (int mt = 0; mt < 2; mt++)
#pragma unroll
                for (int nt = 0; nt < NT; nt++) {
                    mma16816(acc[mt][nt], ah[mt], bh[nt]);
                    mma16816(acc[mt][nt], al[mt], bh[nt]);
                    mma16816(acc[mt][nt], ah[mt], bl[nt]);
                }
        }
    };

    int nCh = K >> 6;
    issue(0, 0); CP_COMMIT();
    for (int kc = 0; kc < nCh; kc++) {
        if (kc + 1 < nCh) { issue(kc + 1, (kc + 1) & 1); CP_COMMIT(); CP_WAIT(1); }
        else CP_WAIT(0);
        __syncthreads();
        compute(kc & 1);
        __syncthreads();
    }

#pragma unroll
    for (int mt = 0; mt < 2; mt++) {
#pragma unroll
        for (int nt = 0; nt < NT; nt++) {
#pragma unroll
            for (int half = 0; half < 2; half++) {
                int r = rowBase + wm*32 + mt*16 + (lane >> 2) + half*8;
#pragma unroll
                for (int q = 0; q < 2; q++) {
                    int c = colBase + wn*(TN/2) + nt*8 + (lane & 3)*2 + q;
                    float v = acc[mt][nt][half*2 + q];
                    size_t o = (size_t)r*Nfull + c;
                    if (MODE == 2) {
                        v = fmaxf(v, 0.f); v *= v;
                        __nv_bfloat16 h, l; split_bf(v, h, l);
                        Chi[o] = h; Clo[o] = l;
                    } else {
                        if (MODE == 1) v += R[o];
                        Cf[o] = v;
                    }
                }
            }
        }
    }
}

// ---------------- prelude ----------------
__global__ void k_prelude(const float* __restrict__ x, const float* __restrict__ x0,
                          const float* __restrict__ lam) {
    int n = blockIdx.x, tid = threadIdx.x;
    __shared__ float red[128];
    float l0 = lam[0], l1 = lam[1];
    float v[4]; float ss = 0.f;
#pragma unroll
    for (int r = 0; r < 4; r++) {
        int d = tid + r*128;
        float t = l0*x[n*DIM+d] + l1*x0[n*DIM+d];
        v[r] = t; g_xr[n*DIM+d] = t; ss += t*t;
    }
    red[tid] = ss; __syncthreads();
    for (int s = 64; s > 0; s >>= 1) { if (tid < s) red[tid] += red[tid+s]; __syncthreads(); }
    float rms = rsqrtf(red[0]*(1.f/512.f) + 1e-6f);
#pragma unroll
    for (int r = 0; r < 4; r++) {
        int d = tid + r*128; float t = v[r]*rms;
        __nv_bfloat16 h, l; split_bf(t, h, l);
        g_xnh[n*DIM+d] = h; g_xnl[n*DIM+d] = l;
    }
}

__global__ void k_rmsnorm2() {
    int n = blockIdx.x, tid = threadIdx.x;
    __shared__ float red[128];
    float v[4]; float ss = 0.f;
#pragma unroll
    for (int r = 0; r < 4; r++) { int d = tid + r*128; float t = g_x2[n*DIM+d]; v[r]=t; ss += t*t; }
    red[tid] = ss; __syncthreads();
    for (int s = 64; s > 0; s >>= 1) { if (tid < s) red[tid] += red[tid+s]; __syncthreads(); }
    float rms = rsqrtf(red[0]*(1.f/512.f) + 1e-6f);
#pragma unroll
    for (int r = 0; r < 4; r++) {
        int d = tid + r*128; float t = v[r]*rms;
        __nv_bfloat16 h, l; split_bf(t, h, l);
        g_xnh[n*DIM+d] = h; g_xnl[n*DIM+d] = l;
    }
}

// ---------------- rope from fused qkv (stride 1600), 4 heads per block ----------------
__global__ void k_rope() {
    int n = blockIdx.x, tid = threadIdx.x;
    int h = blockIdx.y*4 + (tid >> 6), d = tid & 63;
    int src = n*1600 + h*64 + d;
    int dst = (h*NN + n)*64 + d;
    g_v[dst] = g_qkv[src + 1024];
    if (d < 32) {
        float inv = expf(-(float)d * (9.210340371976184f/32.f));
        float ang = (float)n * inv;
        float cs = cosf(ang), sn = sinf(ang);
        float a = g_qkv[src], b = g_qkv[src+32];
        g_q[dst]    = a*cs - b*sn;
        g_q[dst+32] = b*cs + a*sn;
        a = g_qkv[src+512]; b = g_qkv[src+512+32];
        g_k[dst]    = a*cs - b*sn;
        g_k[dst+32] = b*cs + a*sn;
    }
}

// ---------------- compressed K/V: one block per c, all 8 heads, broadcast-LDS ----------------
// block 512 = 8 e-parts x 64 d.  smem: kbs[8][1024], vbs[8][1024], redk/redv[8][8][64]
__global__ void __launch_bounds__(512) k_ckcv(
        const float* __restrict__ kpos, const float* __restrict__ vpos,
        const float* __restrict__ Wck, const float* __restrict__ bck,
        const float* __restrict__ Wcv, const float* __restrict__ bcv,
        const float* __restrict__ kmem, const float* __restrict__ vmem) {
    extern __shared__ float sm[];
    float* kbs = sm;                 // 8192
    float* vbs = sm + 8192;          // 8192
    float* redk = sm + 16384;        // 8*8*64 = 4096
    float* redv = sm + 20480;        // 4096
    int c = blockIdx.x, tid = threadIdx.x;
    for (int idx = tid; idx < 8192; idx += 512) {
        int h = idx >> 10, e = idx & 1023, j = e >> 6, d = e & 63;
        kbs[idx] = g_k[(h*NN + c*16 + j)*64 + d] + kpos[idx];
        vbs[idx] = g_v[(h*NN + c*16 + j)*64 + d] + vpos[idx];
    }
    __syncthreads();
    int part = tid >> 6, d = tid & 63;
    float ak[8] = {}, av[8] = {};
    int e0 = part*128;
    for (int e = e0; e < e0 + 128; e++) {
        float wk = Wck[e*64 + d], wv = Wcv[e*64 + d];
#pragma unroll
        for (int h = 0; h < 8; h++) {
            ak[h] += kbs[h*1024 + e]*wk;
            av[h] += vbs[h*1024 + e]*wv;
        }
    }
#pragma unroll
    for (int h = 0; h < 8; h++) {
        redk[(part*8 + h)*64 + d] = ak[h];
        redv[(part*8 + h)*64 + d] = av[h];
    }
    __syncthreads();
    if (tid < 512) {
        int h = tid >> 6, dd = tid & 63;
        float sk = bck[dd], sv = bcv[dd];
#pragma unroll
        for (int p = 0; p < 8; p++) {
            sk += redk[(p*8 + h)*64 + dd];
            sv += redv[(p*8 + h)*64 + dd];
        }
        g_ckf[(h*65 + 1 + c)*64 + dd] = sk;
        g_cvf[(h*65 + 1 + c)*64 + dd] = sv;
        if (c == 0) {
            g_ckf[h*65*64 + dd] = kmem[h*64 + dd];
            g_cvf[h*65*64 + dd] = vmem[h*64 + dd];
        }
    }
}

// ---------------- compressed attention + top-8 (warp per query) ----------------
__global__ void __launch_bounds__(256) k_compressed() {
    __shared__ float qs[8][64];
    __shared__ float sc[8][72];
    int w = threadIdx.x >> 5, lane = threadIdx.x & 31;
    int i = blockIdx.x*8 + w, h = blockIdx.y;
    int own = i >> 4;
    const float* qp = g_q + (h*NN + i)*64;
    float q0 = qp[lane], q1 = qp[lane + 32];
    qs[w][lane] = q0; qs[w][lane + 32] = q1;
    __syncwarp();
    const float4* q4 = (const float4*)qs[w];
    for (int j = lane; j <= own; j += 32) {
        const float4* kr = (const float4*)(g_ckf + (h*65 + j)*64);
        float acc = 0.f;
#pragma unroll
        for (int d4 = 0; d4 < 16; d4++) {
            float4 kv = kr[d4]; float4 qv = q4[d4];
            acc += qv.x*kv.x + qv.y*kv.y + qv.z*kv.z + qv.w*kv.w;
        }
        sc[w][j] = acc * SCALE;
    }
    __syncwarp();
    float m = -INFINITY;
    for (int j = lane; j <= own; j += 32) m = fmaxf(m, sc[w][j]);
#pragma unroll
    for (int o = 16; o > 0; o >>= 1) m = fmaxf(m, __shfl_xor_sync(0xFFFFFFFFu, m, o));
    float s = 0.f;
    for (int j = lane; j <= own; j += 32) { float e = __expf(sc[w][j] - m); sc[w][j] = e; s += e; }
#pragma unroll
    for (int o = 16; o > 0; o >>= 1) s += __shfl_xor_sync(0xFFFFFFFFu, s, o);
    float inv = 1.f / s;
    __syncwarp();
    float a0 = 0.f, a1 = 0.f;
    for (int j = 0; j <= own; j++) {
        float a = sc[w][j] * inv;
        const float* vr = g_cvf + (h*65 + j)*64;
        a0 += a * vr[lane]; a1 += a * vr[lane + 32];
    }
    g_cout[(h*NN + i)*64 + lane] = a0;
    g_cout[(h*NN + i)*64 + lane + 32] = a1;
    unsigned long long k0 = 0ULL, k1 = 0ULL;
    if (lane < own)
        k0 = ((unsigned long long)__float_as_uint(sc[w][1 + lane]) << 32)
           | (unsigned)(0xFFFFFFFFu - lane);
    if (lane + 32 < own)
        k1 = ((unsigned long long)__float_as_uint(sc[w][1 + lane + 32]) << 32)
           | (unsigned)(0xFFFFFFFFu - (lane + 32));
    int base = (h*NN + i)*8, nv = 0;
#pragma unroll
    for (int t = 0; t < 8; t++) {
        unsigned long long mk = (k0 > k1) ? k0 : k1;
#pragma unroll
        for (int o = 16; o > 0; o >>= 1) {
            unsigned long long other = __shfl_xor_sync(0xFFFFFFFFu, mk, o);
            if (other > mk) mk = other;
        }
        if (mk) {
            int c = (int)(0xFFFFFFFFu - (unsigned)(mk & 0xFFFFFFFFu));
            if (k0 == mk) k0 = 0ULL;
            if (k1 == mk) k1 = 0ULL;
            if (lane == 0) g_sel[base + t] = c;
            nv = t + 1;
        } else if (lane == 0) g_sel[base + t] = 0;
    }
    if (lane == 0) g_nval[h*NN + i] = nv;
}

// ---------------- fine attention (warp per query) ----------------
__global__ void __launch_bounds__(256) k_fine() {
    __shared__ float qs[8][64];
    __shared__ float sc[8][160];
    __shared__ int selS[8][8];
    int w = threadIdx.x >> 5, lane = threadIdx.x & 31;
    int i = blockIdx.x*8 + w, h = blockIdx.y;
    int own = i >> 4, nv = g_nval[h*NN + i], base = (h*NN + i)*8;
    int nk = nv*16 + (i & 15) + 1;
    const float* qp = g_q + (h*NN + i)*64;
    float q0 = qp[lane], q1 = qp[lane + 32];
    qs[w][lane] = q0; qs[w][lane + 32] = q1;
    if (lane < 8) selS[w][lane] = g_sel[base + lane];
    __syncwarp();
    const float4* q4 = (const float4*)qs[w];
    for (int kk = lane; kk < nk; kk += 32) {
        int tok = (kk < nv*16) ? selS[w][kk >> 4]*16 + (kk & 15) : own*16 + (kk - nv*16);
        const float4* kr = (const float4*)(g_k + (h*NN + tok)*64);
        float acc = 0.f;
#pragma unroll
        for (int d4 = 0; d4 < 16; d4++) {
            float4 kv = kr[d4]; float4 qv = q4[d4];
            acc += qv.x*kv.x + qv.y*kv.y + qv.z*kv.z + qv.w*kv.w;
        }
        sc[w][kk] = acc * SCALE;
    }
    __syncwarp();
    float m = -INFINITY;
    for (int kk = lane; kk < nk; kk += 32) m = fmaxf(m, sc[w][kk]);
#pragma unroll
    for (int o = 16; o > 0; o >>= 1) m = fmaxf(m, __shfl_xor_sync(0xFFFFFFFFu, m, o));
    float s = 0.f;
    for (int kk = lane; kk < nk; kk += 32) { float e = __expf(sc[w][kk] - m); sc[w][kk] = e; s += e; }
#pragma unroll
    for (int o = 16; o > 0; o >>= 1) s += __shfl_xor_sync(0xFFFFFFFFu, s, o);
    float inv = 1.f / s;
    __syncwarp();
    float a0 = 0.f, a1 = 0.f;
    for (int kk = 0; kk < nk; kk++) {
        int tok = (kk < nv*16) ? selS[w][kk >> 4]*16 + (kk & 15) : own*16 + (kk - nv*16);
        float a = sc[w][kk] * inv;
        const float* vr = g_v + (h*NN + tok)*64;
        a0 += a * vr[lane]; a1 += a * vr[lane + 32];
    }
    g_fout[(h*NN + i)*64 + lane] = a0;
    g_fout[(h*NN + i)*64 + lane + 32] = a1;
}

// ---------------- sliding window ----------------
__global__ void k_sliding() {
    int qt = blockIdx.x, h = blockIdx.y, tid = threadIdx.x;
    int i0 = qt*16;
    __shared__ float qs[16][65], ks[16][65], vs[16][65], accs[16][64], sc[16][17];
    __shared__ float mrow[16], lrow[16], alpha[16];
#pragma unroll
    for (int r = 0; r < 8; r++) {
        int idx = tid + r*128; int qi = idx >> 6, d = idx & 63;
        qs[qi][d] = g_q[(h*NN + i0 + qi)*64 + d];
        accs[qi][d] = 0.f;
    }
    if (tid < 16) { mrow[tid] = -INFINITY; lrow[tid] = 0.f; }
    __syncthreads();
    int t0 = (qt > 16) ? (qt - 16) : 0;
    for (int t = t0; t <= qt; t++) {
#pragma unroll
        for (int r = 0; r < 8; r++) {
            int idx = tid + r*128; int kj = idx >> 6, d = idx & 63;
            ks[kj][d] = g_k[(h*NN + t*16 + kj)*64 + d];
            vs[kj][d] = g_v[(h*NN + t*16 + kj)*64 + d];
        }
        __syncthreads();
#pragma unroll
        for (int r = 0; r < 2; r++) {
            int p = tid + r*128; int qi = p >> 4, kj = p & 15;
            int j = t*16 + kj, ii = i0 + qi;
            float s = 0.f;
#pragma unroll
            for (int d = 0; d < 64; d++) s += qs[qi][d]*ks[kj][d];
            bool vis = (j <= ii) && (ii - j < 256);
            sc[qi][kj] = vis ? s*SCALE : -INFINITY;
        }
        __syncthreads();
        if (tid < 16) {
            int qi = tid;
            float rm = -INFINITY;
            for (int kj = 0; kj < 16; kj++) rm = fmaxf(rm, sc[qi][kj]);
            float nm = fmaxf(mrow[qi], rm);
            float al, rs = 0.f;
            if (nm == -INFINITY) {
                al = 1.f;
                for (int kj = 0; kj < 16; kj++) sc[qi][kj] = 0.f;
            } else {
                al = __expf(mrow[qi] - nm);
                for (int kj = 0; kj < 16; kj++) {
                    float ee = __expf(sc[qi][kj] - nm);
                    sc[qi][kj] = ee; rs += ee;
                }
            }
            mrow[qi] = nm; alpha[qi] = al; lrow[qi] = lrow[qi]*al + rs;
        }
        __syncthreads();
#pragma unroll
        for (int r = 0; r < 8; r++) {
            int idx = tid + r*128; int qi = idx >> 6, d = idx & 63;
            float a = accs[qi][d]*alpha[qi];
#pragma unroll
            for (int kj = 0; kj < 16; kj++) a += sc[qi][kj]*vs[kj][d];
            accs[qi][d] = a;
        }
        __syncthreads();
    }
#pragma unroll
    for (int r = 0; r < 8; r++) {
        int idx = tid + r*128; int qi = idx >> 6, d = idx & 63;
        g_sout[(h*NN + i0 + qi)*64 + d] = accs[qi][d] / lrow[qi];
    }
}

// ---------------- gated combine -> bf16 hi/lo ----------------
__global__ void k_combine() {
    int n = blockIdx.x, c = threadIdx.x;
    int h = c >> 6, d = c & 63;
    const float* gl = g_qkv + n*1600 + 1536 + h*3;
    float g0 = 1.f/(1.f + __expf(-gl[0]));
    float g1 = 1.f/(1.f + __expf(-gl[1]));
    float g2 = 1.f/(1.f + __expf(-gl[2]));
    int idx = (h*NN + n)*64 + d;
    float v = g0*g_cout[idx] + g1*g_fout[idx] + g2*g_sout[idx];
    __nv_bfloat16 hh, ll; split_bf(v, hh, ll);
    g_ohi[n*DIM + c] = hh; g_olo[n*DIM + c] = ll;
}

// ---------------- launch ----------------
extern "C" void kernel_launch(void* const* d_in, const int* in_sizes, int n_in,
                              void* d_out, int out_size) {
    const float* x    = (const float*)d_in[0];
    const float* x0   = (const float*)d_in[2];
    const float* lam  = (const float*)d_in[3];
    const float* Wq   = (const float*)d_in[4];
    const float* Wk   = (const float*)d_in[5];
    const float* Wv   = (const float*)d_in[6];
    const float* Wo   = (const float*)d_in[7];
    const float* Wg   = (const float*)d_in[8];
    const float* kpos = (const float*)d_in[9];
    const float* vpos = (const float*)d_in[10];
    const float* Wck  = (const float*)d_in[11];
    const float* bck  = (const float*)d_in[12];
    const float* Wcv  = (const float*)d_in[13];
    const float* bcv  = (const float*)d_in[14];
    const float* kmem = (const float*)d_in[15];
    const float* vmem = (const float*)d_in[16];
    const float* W1   = (const float*)d_in[17];
    const float* W2   = (const float*)d_in[18];
    float* out = (float*)d_out;

    float *p_xr, *p_x2, *p_qkv;
    cudaGetSymbolAddress((void**)&p_xr,  g_xr);
    cudaGetSymbolAddress((void**)&p_x2,  g_x2);
    cudaGetSymbolAddress((void**)&p_qkv, g_qkv);
    __nv_bfloat16 *p_xnh,*p_xnl,*p_ohi,*p_olo,*p_hhi,*p_hlo;
    __nv_bfloat16 *p_qkvTh,*p_qkvTl,*p_woTh,*p_woTl,*p_w1Th,*p_w1Tl,*p_w2Th,*p_w2Tl;
    cudaGetSymbolAddress((void**)&p_xnh, g_xnh);  cudaGetSymbolAddress((void**)&p_xnl, g_xnl);
    cudaGetSymbolAddress((void**)&p_ohi, g_ohi);  cudaGetSymbolAddress((void**)&p_olo, g_olo);
    cudaGetSymbolAddress((void**)&p_hhi, g_hhi);  cudaGetSymbolAddress((void**)&p_hlo, g_hlo);
    cudaGetSymbolAddress((void**)&p_qkvTh, g_wqkvTh); cudaGetSymbolAddress((void**)&p_qkvTl, g_wqkvTl);
    cudaGetSymbolAddress((void**)&p_woTh, g_woTh);   cudaGetSymbolAddress((void**)&p_woTl, g_woTl);
    cudaGetSymbolAddress((void**)&p_w1Th, g_w1Th);   cudaGetSymbolAddress((void**)&p_w1Tl, g_w1Tl);
    cudaGetSymbolAddress((void**)&p_w2Th, g_w2Th);   cudaGetSymbolAddress((void**)&p_w2Tl, g_w2Tl);

    const int SMB64 = 2*(32768 + 2*64*128);   // 98304
    const int SMB32 = 2*(32768 + 2*32*128);   // 81920
    const int SMCK  = 24576*4;                // 96KB for k_ckcv
    cudaFuncSetAttribute(hm_gemm<64,0>, cudaFuncAttributeMaxDynamicSharedMemorySize, SMB64);
    cudaFuncSetAttribute(hm_gemm<64,2>, cudaFuncAttributeMaxDynamicSharedMemorySize, SMB64);
    cudaFuncSetAttribute(hm_gemm<32,1>, cudaFuncAttributeMaxDynamicSharedMemorySize, SMB32);
    cudaFuncSetAttribute(k_ckcv, cudaFuncAttributeMaxDynamicSharedMemorySize, SMCK);

    k_convAll<<<3104, dim3(32,8)>>>(Wq, Wk, Wv, Wo, W1, W2, Wg);
    k_prelude<<<NN, 128>>>(x, x0, lam);

    // fused QKV+gates: [1024,512] @ [512,1600]
    hm_gemm<64,0><<<dim3(25,8), 256, SMB64>>>(p_xnh, p_xnl, p_qkvTh, p_qkvTl,
                                              nullptr, p_qkv, nullptr, nullptr, 512, 1600);

    k_rope<<<dim3(NN, 2), 256>>>();
    k_ckcv<<<CC, 512, SMCK>>>(kpos, vpos, Wck, bck, Wcv, bcv, kmem, vmem);

    k_compressed<<<dim3(NN/8, HH), 256>>>();
    k_fine<<<dim3(NN/8, HH), 256>>>();
    k_sliding<<<dim3(NN/16, HH), 128>>>();
    k_combine<<<NN, 512>>>();

    // x2 = xr + o @ Wo
    hm_gemm<32,1><<<dim3(16,8), 256, SMB32>>>(p_ohi, p_olo, p_woTh, p_woTl,
                                              p_xr, p_x2, nullptr, nullptr, 512, 512);
    k_rmsnorm2<<<NN, 128>>>();
    // h = relu(xn2 @ W1)^2 -> bf16 hi/lo
    hm_gemm<64,2><<<dim3(32,8), 256, SMB64>>>(p_xnh, p_xnl, p_w1Th, p_w1Tl,
                                              nullptr, nullptr, p_hhi, p_hlo, 512, 2048);
    // out = x2 + h @ W2
    hm_gemm<32,1><<<dim3(16,8), 256, SMB32>>>(p_hhi, p_hlo, p_w2Th, p_w2Tl,
                                              p_x2, out, nullptr, nullptr, 2048, 512);
}